// round 1
// baseline (speedup 1.0000x reference)
#include <cuda_runtime.h>

#define B_ 8
#define N_ 1024
#define D_ 768
#define H_ 12
#define HD_ 64

// Scratch (allocation-free rule: __device__ globals)
__device__ float g_q[B_ * H_ * N_ * HD_];
__device__ float g_k[B_ * H_ * N_ * HD_];
__device__ float g_v[B_ * H_ * N_ * HD_];
__device__ float g_att[B_ * H_ * N_ * HD_];

// ---------------------------------------------------------------------------
// Kernel 1: per-head QKV projection.
// q[b,h,n,e] = sum_d x[b,n,h*64+d] * Wq[h,d,e] + bq[h,e]   (same for k,v)
// grid (16, 96) = (n-tile, b*H+h), block 256 (16x16), 4x4 register tile.
// ---------------------------------------------------------------------------
__global__ __launch_bounds__(256) void qkv_kernel(
    const float* __restrict__ x,
    const float* __restrict__ Wq, const float* __restrict__ Wk, const float* __restrict__ Wv,
    const float* __restrict__ bq, const float* __restrict__ bk, const float* __restrict__ bv)
{
    __shared__ __align__(16) float Xs[64][68];
    __shared__ __align__(16) float Ws[64][68];

    const int bh = blockIdx.y;
    const int h  = bh % H_;
    const int b  = bh / H_;
    const int n0 = blockIdx.x * 64;
    const int t  = threadIdx.x;
    const int ty = t >> 4, tx = t & 15;

#pragma unroll
    for (int k = 0; k < 16; k++) {
        int idx = t + k * 256;
        int r = idx >> 6, d = idx & 63;
        Xs[r][d] = x[(b * N_ + n0 + r) * D_ + h * HD_ + d];
    }

    const float* Wm[3] = {Wq, Wk, Wv};
    const float* bm[3] = {bq, bk, bv};
    float*       om[3] = {g_q, g_k, g_v};

    for (int m = 0; m < 3; m++) {
        __syncthreads();
        const float* W = Wm[m] + h * HD_ * HD_;
#pragma unroll
        for (int k = 0; k < 16; k++) {
            int idx = t + k * 256;
            Ws[idx >> 6][idx & 63] = W[idx];
        }
        __syncthreads();

        float acc[4][4];
#pragma unroll
        for (int j = 0; j < 4; j++) {
            float bb = bm[m][h * HD_ + 4 * tx + j];
#pragma unroll
            for (int i = 0; i < 4; i++) acc[i][j] = bb;
        }

#pragma unroll 8
        for (int d = 0; d < 64; d++) {
            float av0 = Xs[4 * ty + 0][d];
            float av1 = Xs[4 * ty + 1][d];
            float av2 = Xs[4 * ty + 2][d];
            float av3 = Xs[4 * ty + 3][d];
            float4 wv = *(const float4*)&Ws[d][4 * tx];
            acc[0][0] += av0 * wv.x; acc[0][1] += av0 * wv.y; acc[0][2] += av0 * wv.z; acc[0][3] += av0 * wv.w;
            acc[1][0] += av1 * wv.x; acc[1][1] += av1 * wv.y; acc[1][2] += av1 * wv.z; acc[1][3] += av1 * wv.w;
            acc[2][0] += av2 * wv.x; acc[2][1] += av2 * wv.y; acc[2][2] += av2 * wv.z; acc[2][3] += av2 * wv.w;
            acc[3][0] += av3 * wv.x; acc[3][1] += av3 * wv.y; acc[3][2] += av3 * wv.z; acc[3][3] += av3 * wv.w;
        }

        float* o = om[m] + (bh * N_ + n0) * HD_;
#pragma unroll
        for (int i = 0; i < 4; i++) {
            float4 v4 = make_float4(acc[i][0], acc[i][1], acc[i][2], acc[i][3]);
            *(float4*)&o[(4 * ty + i) * HD_ + 4 * tx] = v4;
        }
    }
}

// ---------------------------------------------------------------------------
// Kernel 2: flash attention per (b,h). grid (16, 96) = (q-tile, b*H+h).
// block 256 (16x16), 64x64 tiles, online softmax, 4x4 register tiles.
// K stored transposed in smem; its buffer is reused for P.
// ---------------------------------------------------------------------------
__global__ __launch_bounds__(256) void attn_kernel()
{
    extern __shared__ __align__(16) float sm[];
    float (*Qs)[68]  = (float(*)[68])sm;                 // [64][68]  Q (scaled)
    float (*KPs)[68] = (float(*)[68])(sm + 64 * 68);     // [64][68]  K^T, then P
    float (*Vs)[68]  = (float(*)[68])(sm + 2 * 64 * 68); // [64][68]  V

    const int bh = blockIdx.y;
    const int q0 = blockIdx.x * 64;
    const int t  = threadIdx.x;
    const int ty = t >> 4, tx = t & 15;

    const float scale = rsqrtf((float)D_);   // quirk: full-dim scale
    const float* Q = g_q + (size_t)bh * N_ * HD_;
    const float* K = g_k + (size_t)bh * N_ * HD_;
    const float* V = g_v + (size_t)bh * N_ * HD_;

#pragma unroll
    for (int k = 0; k < 16; k++) {
        int idx = t + k * 256;
        int r = idx >> 6, d = idx & 63;
        Qs[r][d] = Q[(q0 + r) * HD_ + d] * scale;
    }

    float mrow[4], lrow[4], O[4][4];
#pragma unroll
    for (int i = 0; i < 4; i++) {
        mrow[i] = -1e30f; lrow[i] = 0.f;
#pragma unroll
        for (int j = 0; j < 4; j++) O[i][j] = 0.f;
    }

    for (int kt = 0; kt < N_ / 64; kt++) {
        __syncthreads();  // previous iter's smem reads complete
#pragma unroll
        for (int k = 0; k < 16; k++) {
            int idx = t + k * 256;
            int r = idx >> 6, d = idx & 63;
            float kvel = K[(kt * 64 + r) * HD_ + d];
            float vvel = V[(kt * 64 + r) * HD_ + d];
            KPs[d][r] = kvel;   // transposed
            Vs[r][d]  = vvel;
        }
        __syncthreads();

        // S = Q K^T (scale already folded into Q)
        float S[4][4];
#pragma unroll
        for (int i = 0; i < 4; i++)
#pragma unroll
            for (int j = 0; j < 4; j++) S[i][j] = 0.f;

#pragma unroll 8
        for (int d = 0; d < 64; d++) {
            float q0v = Qs[4 * ty + 0][d];
            float q1v = Qs[4 * ty + 1][d];
            float q2v = Qs[4 * ty + 2][d];
            float q3v = Qs[4 * ty + 3][d];
            float4 kv = *(const float4*)&KPs[d][4 * tx];
            S[0][0] += q0v * kv.x; S[0][1] += q0v * kv.y; S[0][2] += q0v * kv.z; S[0][3] += q0v * kv.w;
            S[1][0] += q1v * kv.x; S[1][1] += q1v * kv.y; S[1][2] += q1v * kv.z; S[1][3] += q1v * kv.w;
            S[2][0] += q2v * kv.x; S[2][1] += q2v * kv.y; S[2][2] += q2v * kv.z; S[2][3] += q2v * kv.w;
            S[3][0] += q3v * kv.x; S[3][1] += q3v * kv.y; S[3][2] += q3v * kv.z; S[3][3] += q3v * kv.w;
        }

        // online softmax per row (row group = 16 threads sharing ty; lanes form
        // an aligned 16-lane segment, so width-16 xor shuffles reduce the row)
#pragma unroll
        for (int i = 0; i < 4; i++) {
            float rm = fmaxf(fmaxf(S[i][0], S[i][1]), fmaxf(S[i][2], S[i][3]));
#pragma unroll
            for (int o = 8; o >= 1; o >>= 1)
                rm = fmaxf(rm, __shfl_xor_sync(0xffffffffu, rm, o, 16));
            float nm   = fmaxf(mrow[i], rm);
            float corr = __expf(mrow[i] - nm);
            float rs = 0.f;
#pragma unroll
            for (int j = 0; j < 4; j++) {
                S[i][j] = __expf(S[i][j] - nm);
                rs += S[i][j];
            }
#pragma unroll
            for (int o = 8; o >= 1; o >>= 1)
                rs += __shfl_xor_sync(0xffffffffu, rs, o, 16);
            lrow[i] = lrow[i] * corr + rs;
            mrow[i] = nm;
#pragma unroll
            for (int j = 0; j < 4; j++) O[i][j] *= corr;
        }

        __syncthreads();  // all reads of KPs-as-K done
#pragma unroll
        for (int i = 0; i < 4; i++)
#pragma unroll
            for (int j = 0; j < 4; j++) KPs[4 * ty + i][4 * tx + j] = S[i][j];
        __syncthreads();

        // O += P @ V
#pragma unroll 8
        for (int jj = 0; jj < 64; jj++) {
            float p0 = KPs[4 * ty + 0][jj];
            float p1 = KPs[4 * ty + 1][jj];
            float p2 = KPs[4 * ty + 2][jj];
            float p3 = KPs[4 * ty + 3][jj];
            float4 vv = *(const float4*)&Vs[jj][4 * tx];
            O[0][0] += p0 * vv.x; O[0][1] += p0 * vv.y; O[0][2] += p0 * vv.z; O[0][3] += p0 * vv.w;
            O[1][0] += p1 * vv.x; O[1][1] += p1 * vv.y; O[1][2] += p1 * vv.z; O[1][3] += p1 * vv.w;
            O[2][0] += p2 * vv.x; O[2][1] += p2 * vv.y; O[2][2] += p2 * vv.z; O[2][3] += p2 * vv.w;
            O[3][0] += p3 * vv.x; O[3][1] += p3 * vv.y; O[3][2] += p3 * vv.z; O[3][3] += p3 * vv.w;
        }
    }

    float* Ao = g_att + ((size_t)bh * N_ + q0) * HD_;
#pragma unroll
    for (int i = 0; i < 4; i++) {
        float inv = 1.f / lrow[i];
        float4 v4 = make_float4(O[i][0] * inv, O[i][1] * inv, O[i][2] * inv, O[i][3] * inv);
        *(float4*)&Ao[(4 * ty + i) * HD_ + 4 * tx] = v4;
    }
}

// ---------------------------------------------------------------------------
// Kernel 3: output projection. out[bn, f] = sum_k concat[bn,k] * Wo[f,k] + bo[f]
// concat[b,n,h*64+e] = g_att[b,h,n,e]; K-tiles align exactly with heads.
// grid (12, 128) = (col tile, row tile), block 256, 4x4 register tiles.
// ---------------------------------------------------------------------------
__global__ __launch_bounds__(256) void outproj_kernel(
    const float* __restrict__ Wo, const float* __restrict__ bo,
    float* __restrict__ out)
{
    __shared__ __align__(16) float As[64][68];   // As[r][kk]  activation rows
    __shared__ __align__(16) float Bs[64][68];   // Bs[kk][c] = Wo[c0+c][k0+kk]

    const int c0 = blockIdx.x * 64;
    const int r0 = blockIdx.y * 64;
    const int b  = r0 / N_;
    const int n0 = r0 % N_;
    const int t  = threadIdx.x;
    const int ty = t >> 4, tx = t & 15;

    float acc[4][4];
#pragma unroll
    for (int j = 0; j < 4; j++) {
        float bb = bo[c0 + 4 * tx + j];
#pragma unroll
        for (int i = 0; i < 4; i++) acc[i][j] = bb;
    }

    for (int kt = 0; kt < H_; kt++) {   // k-tile == head
        __syncthreads();
#pragma unroll
        for (int k = 0; k < 16; k++) {
            int idx = t + k * 256;
            int r = idx >> 6, kk = idx & 63;
            As[r][kk] = g_att[(((size_t)b * H_ + kt) * N_ + n0 + r) * HD_ + kk];
            Bs[kk][r] = Wo[(c0 + r) * D_ + kt * 64 + kk];
        }
        __syncthreads();

#pragma unroll 8
        for (int kk = 0; kk < 64; kk++) {
            float a0 = As[4 * ty + 0][kk];
            float a1 = As[4 * ty + 1][kk];
            float a2 = As[4 * ty + 2][kk];
            float a3 = As[4 * ty + 3][kk];
            float4 wv = *(const float4*)&Bs[kk][4 * tx];
            acc[0][0] += a0 * wv.x; acc[0][1] += a0 * wv.y; acc[0][2] += a0 * wv.z; acc[0][3] += a0 * wv.w;
            acc[1][0] += a1 * wv.x; acc[1][1] += a1 * wv.y; acc[1][2] += a1 * wv.z; acc[1][3] += a1 * wv.w;
            acc[2][0] += a2 * wv.x; acc[2][1] += a2 * wv.y; acc[2][2] += a2 * wv.z; acc[2][3] += a2 * wv.w;
            acc[3][0] += a3 * wv.x; acc[3][1] += a3 * wv.y; acc[3][2] += a3 * wv.z; acc[3][3] += a3 * wv.w;
        }
    }

#pragma unroll
    for (int i = 0; i < 4; i++) {
        float4 v4 = make_float4(acc[i][0], acc[i][1], acc[i][2], acc[i][3]);
        *(float4*)&out[(r0 + 4 * ty + i) * D_ + c0 + 4 * tx] = v4;
    }
}

// ---------------------------------------------------------------------------
extern "C" void kernel_launch(void* const* d_in, const int* in_sizes, int n_in,
                              void* d_out, int out_size)
{
    const float* x  = (const float*)d_in[0];
    const float* Wq = (const float*)d_in[1];
    const float* Wk = (const float*)d_in[2];
    const float* Wv = (const float*)d_in[3];
    const float* bq = (const float*)d_in[4];
    const float* bk = (const float*)d_in[5];
    const float* bv = (const float*)d_in[6];
    const float* Wo = (const float*)d_in[7];
    const float* bo = (const float*)d_in[8];
    float* out = (float*)d_out;

    const int attn_smem = 3 * 64 * 68 * (int)sizeof(float);  // 52224 B
    cudaFuncSetAttribute(attn_kernel, cudaFuncAttributeMaxDynamicSharedMemorySize, attn_smem);

    qkv_kernel<<<dim3(16, B_ * H_), 256>>>(x, Wq, Wk, Wv, bq, bk, bv);
    attn_kernel<<<dim3(16, B_ * H_), 256, attn_smem>>>();
    outproj_kernel<<<dim3(D_ / 64, (B_ * N_) / 64), 256>>>(Wo, bo, out);
}

// round 2
// speedup vs baseline: 1.7424x; 1.7424x over previous
#include <cuda_runtime.h>
#include <cstdint>

#define B_ 8
#define N_ 1024
#define D_ 768
#define H_ 12
#define HD_ 64

// Scratch (allocation-free rule: __device__ globals)
__device__ float g_q[B_ * H_ * N_ * HD_];
__device__ float g_k[B_ * H_ * N_ * HD_];
__device__ float g_v[B_ * H_ * N_ * HD_];
__device__ float g_att[B_ * H_ * N_ * HD_];

// ---------------------------------------------------------------------------
// helpers
// ---------------------------------------------------------------------------
__device__ __forceinline__ float tf32r(float x) {
    uint32_t u;
    asm("cvt.rna.tf32.f32 %0, %1;" : "=r"(u) : "f"(x));
    return __uint_as_float(u);
}

__device__ __forceinline__ void mma_tf32(float c[4],
                                         uint32_t a0, uint32_t a1, uint32_t a2, uint32_t a3,
                                         uint32_t b0, uint32_t b1) {
    asm volatile(
        "mma.sync.aligned.m16n8k8.row.col.f32.tf32.tf32.f32 "
        "{%0,%1,%2,%3},{%4,%5,%6,%7},{%8,%9},{%0,%1,%2,%3};\n"
        : "+f"(c[0]), "+f"(c[1]), "+f"(c[2]), "+f"(c[3])
        : "r"(a0), "r"(a1), "r"(a2), "r"(a3), "r"(b0), "r"(b1));
}

// ---------------------------------------------------------------------------
// Kernel 1: per-head QKV projection (fp32, unchanged from R1).
// ---------------------------------------------------------------------------
__global__ __launch_bounds__(256) void qkv_kernel(
    const float* __restrict__ x,
    const float* __restrict__ Wq, const float* __restrict__ Wk, const float* __restrict__ Wv,
    const float* __restrict__ bq, const float* __restrict__ bk, const float* __restrict__ bv)
{
    __shared__ __align__(16) float Xs[64][68];
    __shared__ __align__(16) float Ws[64][68];

    const int bh = blockIdx.y;
    const int h  = bh % H_;
    const int b  = bh / H_;
    const int n0 = blockIdx.x * 64;
    const int t  = threadIdx.x;
    const int ty = t >> 4, tx = t & 15;

#pragma unroll
    for (int k = 0; k < 16; k++) {
        int idx = t + k * 256;
        int r = idx >> 6, d = idx & 63;
        Xs[r][d] = x[(b * N_ + n0 + r) * D_ + h * HD_ + d];
    }

    const float* Wm[3] = {Wq, Wk, Wv};
    const float* bm[3] = {bq, bk, bv};
    float*       om[3] = {g_q, g_k, g_v};

    for (int m = 0; m < 3; m++) {
        __syncthreads();
        const float* W = Wm[m] + h * HD_ * HD_;
#pragma unroll
        for (int k = 0; k < 16; k++) {
            int idx = t + k * 256;
            Ws[idx >> 6][idx & 63] = W[idx];
        }
        __syncthreads();

        float acc[4][4];
#pragma unroll
        for (int j = 0; j < 4; j++) {
            float bb = bm[m][h * HD_ + 4 * tx + j];
#pragma unroll
            for (int i = 0; i < 4; i++) acc[i][j] = bb;
        }

#pragma unroll 8
        for (int d = 0; d < 64; d++) {
            float av0 = Xs[4 * ty + 0][d];
            float av1 = Xs[4 * ty + 1][d];
            float av2 = Xs[4 * ty + 2][d];
            float av3 = Xs[4 * ty + 3][d];
            float4 wv = *(const float4*)&Ws[d][4 * tx];
            acc[0][0] += av0 * wv.x; acc[0][1] += av0 * wv.y; acc[0][2] += av0 * wv.z; acc[0][3] += av0 * wv.w;
            acc[1][0] += av1 * wv.x; acc[1][1] += av1 * wv.y; acc[1][2] += av1 * wv.z; acc[1][3] += av1 * wv.w;
            acc[2][0] += av2 * wv.x; acc[2][1] += av2 * wv.y; acc[2][2] += av2 * wv.z; acc[2][3] += av2 * wv.w;
            acc[3][0] += av3 * wv.x; acc[3][1] += av3 * wv.y; acc[3][2] += av3 * wv.z; acc[3][3] += av3 * wv.w;
        }

        float* o = om[m] + (bh * N_ + n0) * HD_;
#pragma unroll
        for (int i = 0; i < 4; i++) {
            float4 v4 = make_float4(acc[i][0], acc[i][1], acc[i][2], acc[i][3]);
            *(float4*)&o[(4 * ty + i) * HD_ + 4 * tx] = v4;
        }
    }
}

// ---------------------------------------------------------------------------
// Kernel 2: flash attention with tf32 mma.sync tensor cores.
// grid (8, 96) = (q-tile of 128, b*H+h). block 256 = 8 warps.
// Warp w owns q-rows [16w, 16w+16). KV tiles of 64. Online softmax on
// MMA fragments; P goes through smem (warp-local, syncwarp only).
// smem strides: Q/K/P = 68 (conflict-free B/A frag loads), V = 72.
// ---------------------------------------------------------------------------
__global__ __launch_bounds__(256, 2) void attn_mma_kernel()
{
    extern __shared__ __align__(16) float sm[];
    float* Qs = sm;                       // [128][68]
    float* Ks = Qs + 128 * 68;            // [64][68]
    float* Ps = Ks + 64 * 68;             // [128][68]
    float* Vs = Ps + 128 * 68;            // [64][72]
    const uint32_t* Qu = (const uint32_t*)Qs;
    const uint32_t* Ku = (const uint32_t*)Ks;
    const uint32_t* Pu = (const uint32_t*)Ps;
    const uint32_t* Vu = (const uint32_t*)Vs;

    const int bh = blockIdx.y;
    const int q0 = blockIdx.x * 128;
    const int t  = threadIdx.x;
    const int w  = t >> 5;
    const int lane = t & 31;
    const int g  = lane >> 2;   // groupID (row within fragment)
    const int qd = lane & 3;    // quad lane

    const float scale = rsqrtf((float)D_);   // quirk: full-dim scale
    const float* Qg = g_q + (size_t)bh * N_ * HD_;
    const float* Kg = g_k + (size_t)bh * N_ * HD_;
    const float* Vg = g_v + (size_t)bh * N_ * HD_;

    // load + scale + tf32-round Q tile [128][64]
#pragma unroll
    for (int i = t; i < 128 * 16; i += 256) {
        int r = i >> 4, c4 = (i & 15) << 2;
        float4 v = *(const float4*)&Qg[(q0 + r) * HD_ + c4];
        v.x = tf32r(v.x * scale); v.y = tf32r(v.y * scale);
        v.z = tf32r(v.z * scale); v.w = tf32r(v.w * scale);
        *(float4*)&Qs[r * 68 + c4] = v;
    }

    const int row0 = w * 16 + g;            // local q-row for c0/c1 (c2/c3: +8)

    float O[8][4];
#pragma unroll
    for (int dt = 0; dt < 8; dt++)
#pragma unroll
        for (int j = 0; j < 4; j++) O[dt][j] = 0.f;
    float m0 = -1e30f, m1 = -1e30f, l0 = 0.f, l1 = 0.f;

    for (int kt = 0; kt < N_ / 64; kt++) {
        __syncthreads();  // prior-iter smem reads complete
#pragma unroll
        for (int i = t; i < 64 * 16; i += 256) {
            int r = i >> 4, c4 = (i & 15) << 2;
            float4 kv = *(const float4*)&Kg[(kt * 64 + r) * HD_ + c4];
            float4 vv = *(const float4*)&Vg[(kt * 64 + r) * HD_ + c4];
            kv.x = tf32r(kv.x); kv.y = tf32r(kv.y); kv.z = tf32r(kv.z); kv.w = tf32r(kv.w);
            vv.x = tf32r(vv.x); vv.y = tf32r(vv.y); vv.z = tf32r(vv.z); vv.w = tf32r(vv.w);
            *(float4*)&Ks[r * 68 + c4] = kv;
            *(float4*)&Vs[r * 72 + c4] = vv;
        }
        __syncthreads();

        // ---- S = Q K^T : 16 q-rows x 64 keys per warp ----
        float S[8][4];
#pragma unroll
        for (int nt = 0; nt < 8; nt++)
#pragma unroll
            for (int j = 0; j < 4; j++) S[nt][j] = 0.f;

#pragma unroll
        for (int kc = 0; kc < 8; kc++) {
            uint32_t a0 = Qu[(row0)     * 68 + kc * 8 + qd];
            uint32_t a1 = Qu[(row0 + 8) * 68 + kc * 8 + qd];
            uint32_t a2 = Qu[(row0)     * 68 + kc * 8 + qd + 4];
            uint32_t a3 = Qu[(row0 + 8) * 68 + kc * 8 + qd + 4];
#pragma unroll
            for (int nt = 0; nt < 8; nt++) {
                uint32_t b0 = Ku[(nt * 8 + g) * 68 + kc * 8 + qd];
                uint32_t b1 = Ku[(nt * 8 + g) * 68 + kc * 8 + qd + 4];
                mma_tf32(S[nt], a0, a1, a2, a3, b0, b1);
            }
        }

        // ---- online softmax (rows row0 and row0+8) ----
        float mx0 = -1e30f, mx1 = -1e30f;
#pragma unroll
        for (int nt = 0; nt < 8; nt++) {
            mx0 = fmaxf(mx0, fmaxf(S[nt][0], S[nt][1]));
            mx1 = fmaxf(mx1, fmaxf(S[nt][2], S[nt][3]));
        }
        mx0 = fmaxf(mx0, __shfl_xor_sync(0xffffffffu, mx0, 1));
        mx0 = fmaxf(mx0, __shfl_xor_sync(0xffffffffu, mx0, 2));
        mx1 = fmaxf(mx1, __shfl_xor_sync(0xffffffffu, mx1, 1));
        mx1 = fmaxf(mx1, __shfl_xor_sync(0xffffffffu, mx1, 2));

        float nm0 = fmaxf(m0, mx0), nm1 = fmaxf(m1, mx1);
        float corr0 = __expf(m0 - nm0), corr1 = __expf(m1 - nm1);
        m0 = nm0; m1 = nm1;

        float s0 = 0.f, s1 = 0.f;
#pragma unroll
        for (int nt = 0; nt < 8; nt++) {
            S[nt][0] = __expf(S[nt][0] - nm0);
            S[nt][1] = __expf(S[nt][1] - nm0);
            S[nt][2] = __expf(S[nt][2] - nm1);
            S[nt][3] = __expf(S[nt][3] - nm1);
            s0 += S[nt][0] + S[nt][1];
            s1 += S[nt][2] + S[nt][3];
        }
        s0 += __shfl_xor_sync(0xffffffffu, s0, 1);
        s0 += __shfl_xor_sync(0xffffffffu, s0, 2);
        s1 += __shfl_xor_sync(0xffffffffu, s1, 1);
        s1 += __shfl_xor_sync(0xffffffffu, s1, 2);
        l0 = l0 * corr0 + s0;
        l1 = l1 * corr1 + s1;

#pragma unroll
        for (int dt = 0; dt < 8; dt++) {
            O[dt][0] *= corr0; O[dt][1] *= corr0;
            O[dt][2] *= corr1; O[dt][3] *= corr1;
        }

        // ---- P -> smem (warp-local rows only) ----
#pragma unroll
        for (int nt = 0; nt < 8; nt++) {
            Ps[(row0)     * 68 + nt * 8 + 2 * qd]     = tf32r(S[nt][0]);
            Ps[(row0)     * 68 + nt * 8 + 2 * qd + 1] = tf32r(S[nt][1]);
            Ps[(row0 + 8) * 68 + nt * 8 + 2 * qd]     = tf32r(S[nt][2]);
            Ps[(row0 + 8) * 68 + nt * 8 + 2 * qd + 1] = tf32r(S[nt][3]);
        }
        __syncwarp();

        // ---- O += P V ----
#pragma unroll
        for (int kc = 0; kc < 8; kc++) {
            uint32_t a0 = Pu[(row0)     * 68 + kc * 8 + qd];
            uint32_t a1 = Pu[(row0 + 8) * 68 + kc * 8 + qd];
            uint32_t a2 = Pu[(row0)     * 68 + kc * 8 + qd + 4];
            uint32_t a3 = Pu[(row0 + 8) * 68 + kc * 8 + qd + 4];
#pragma unroll
            for (int dt = 0; dt < 8; dt++) {
                uint32_t b0 = Vu[(kc * 8 + qd)     * 72 + dt * 8 + g];
                uint32_t b1 = Vu[(kc * 8 + qd + 4) * 72 + dt * 8 + g];
                mma_tf32(O[dt], a0, a1, a2, a3, b0, b1);
            }
        }
        __syncwarp();  // Ps reads done before next-iter rewrite
    }

    // ---- normalize + store ----
    float inv0 = 1.f / l0, inv1 = 1.f / l1;
    float* Ao = g_att + ((size_t)bh * N_ + q0) * HD_;
#pragma unroll
    for (int dt = 0; dt < 8; dt++) {
        float2 u0 = make_float2(O[dt][0] * inv0, O[dt][1] * inv0);
        float2 u1 = make_float2(O[dt][2] * inv1, O[dt][3] * inv1);
        *(float2*)&Ao[(row0)     * HD_ + dt * 8 + 2 * qd] = u0;
        *(float2*)&Ao[(row0 + 8) * HD_ + dt * 8 + 2 * qd] = u1;
    }
}

// ---------------------------------------------------------------------------
// Kernel 3: output projection (fp32, unchanged from R1).
// ---------------------------------------------------------------------------
__global__ __launch_bounds__(256) void outproj_kernel(
    const float* __restrict__ Wo, const float* __restrict__ bo,
    float* __restrict__ out)
{
    __shared__ __align__(16) float As[64][68];
    __shared__ __align__(16) float Bs[64][68];

    const int c0 = blockIdx.x * 64;
    const int r0 = blockIdx.y * 64;
    const int b  = r0 / N_;
    const int n0 = r0 % N_;
    const int t  = threadIdx.x;
    const int ty = t >> 4, tx = t & 15;

    float acc[4][4];
#pragma unroll
    for (int j = 0; j < 4; j++) {
        float bb = bo[c0 + 4 * tx + j];
#pragma unroll
        for (int i = 0; i < 4; i++) acc[i][j] = bb;
    }

    for (int kt = 0; kt < H_; kt++) {
        __syncthreads();
#pragma unroll
        for (int k = 0; k < 16; k++) {
            int idx = t + k * 256;
            int r = idx >> 6, kk = idx & 63;
            As[r][kk] = g_att[(((size_t)b * H_ + kt) * N_ + n0 + r) * HD_ + kk];
            Bs[kk][r] = Wo[(c0 + r) * D_ + kt * 64 + kk];
        }
        __syncthreads();

#pragma unroll 8
        for (int kk = 0; kk < 64; kk++) {
            float a0 = As[4 * ty + 0][kk];
            float a1 = As[4 * ty + 1][kk];
            float a2 = As[4 * ty + 2][kk];
            float a3 = As[4 * ty + 3][kk];
            float4 wv = *(const float4*)&Bs[kk][4 * tx];
            acc[0][0] += a0 * wv.x; acc[0][1] += a0 * wv.y; acc[0][2] += a0 * wv.z; acc[0][3] += a0 * wv.w;
            acc[1][0] += a1 * wv.x; acc[1][1] += a1 * wv.y; acc[1][2] += a1 * wv.z; acc[1][3] += a1 * wv.w;
            acc[2][0] += a2 * wv.x; acc[2][1] += a2 * wv.y; acc[2][2] += a2 * wv.z; acc[2][3] += a2 * wv.w;
            acc[3][0] += a3 * wv.x; acc[3][1] += a3 * wv.y; acc[3][2] += a3 * wv.z; acc[3][3] += a3 * wv.w;
        }
    }

#pragma unroll
    for (int i = 0; i < 4; i++) {
        float4 v4 = make_float4(acc[i][0], acc[i][1], acc[i][2], acc[i][3]);
        *(float4*)&out[(r0 + 4 * ty + i) * D_ + c0 + 4 * tx] = v4;
    }
}

// ---------------------------------------------------------------------------
extern "C" void kernel_launch(void* const* d_in, const int* in_sizes, int n_in,
                              void* d_out, int out_size)
{
    const float* x  = (const float*)d_in[0];
    const float* Wq = (const float*)d_in[1];
    const float* Wk = (const float*)d_in[2];
    const float* Wv = (const float*)d_in[3];
    const float* bq = (const float*)d_in[4];
    const float* bk = (const float*)d_in[5];
    const float* bv = (const float*)d_in[6];
    const float* Wo = (const float*)d_in[7];
    const float* bo = (const float*)d_in[8];
    float* out = (float*)d_out;

    const int attn_smem = (128 * 68 + 64 * 68 + 128 * 68 + 64 * 72) * (int)sizeof(float); // 105472
    cudaFuncSetAttribute(attn_mma_kernel, cudaFuncAttributeMaxDynamicSharedMemorySize, attn_smem);

    qkv_kernel<<<dim3(16, B_ * H_), 256>>>(x, Wq, Wk, Wv, bq, bk, bv);
    attn_mma_kernel<<<dim3(N_ / 128, B_ * H_), 256, attn_smem>>>();
    outproj_kernel<<<dim3(D_ / 64, (B_ * N_) / 64), 256>>>(Wo, bo, out);
}

// round 3
// speedup vs baseline: 2.7054x; 1.5526x over previous
#include <cuda_runtime.h>
#include <cstdint>

#define B_ 8
#define N_ 1024
#define D_ 768
#define H_ 12
#define HD_ 64

// Scratch (allocation-free rule: __device__ globals)
__device__ float g_q[B_ * H_ * N_ * HD_];
__device__ float g_k[B_ * H_ * N_ * HD_];
__device__ float g_v[B_ * H_ * N_ * HD_];
__device__ float g_att[B_ * N_ * D_];   // concat layout [B*N, D]

// ---------------------------------------------------------------------------
// helpers
// ---------------------------------------------------------------------------
__device__ __forceinline__ float tf32r(float x) {
    uint32_t u;
    asm("cvt.rna.tf32.f32 %0, %1;" : "=r"(u) : "f"(x));
    return __uint_as_float(u);
}

__device__ __forceinline__ void mma_tf32(float c[4],
                                         uint32_t a0, uint32_t a1, uint32_t a2, uint32_t a3,
                                         uint32_t b0, uint32_t b1) {
    asm volatile(
        "mma.sync.aligned.m16n8k8.row.col.f32.tf32.tf32.f32 "
        "{%0,%1,%2,%3},{%4,%5,%6,%7},{%8,%9},{%0,%1,%2,%3};\n"
        : "+f"(c[0]), "+f"(c[1]), "+f"(c[2]), "+f"(c[3])
        : "r"(a0), "r"(a1), "r"(a2), "r"(a3), "r"(b0), "r"(b1));
}

// ---------------------------------------------------------------------------
// Kernel 1: per-head QKV projection, tf32 mma.
// grid (8, 96) = (row tile of 128, b*H+h). block 256 = 8 warps.
// q[n,e] = sum_d X[n,d] W[d,e] + b[e].  X tile loaded once, reused for q/k/v.
// Outputs stored pre-rounded to tf32.
// ---------------------------------------------------------------------------
__global__ __launch_bounds__(256) void qkv_mma_kernel(
    const float* __restrict__ x,
    const float* __restrict__ Wq, const float* __restrict__ Wk, const float* __restrict__ Wv,
    const float* __restrict__ bq, const float* __restrict__ bk, const float* __restrict__ bv)
{
    extern __shared__ __align__(16) float sm[];
    float* Xs = sm;               // [128][68]
    float* Ws = Xs + 128 * 68;    // [64][68]  transposed: Ws[e][d]
    const uint32_t* Xu = (const uint32_t*)Xs;
    const uint32_t* Wu = (const uint32_t*)Ws;

    const int bh = blockIdx.y;
    const int h  = bh % H_;
    const int b  = bh / H_;
    const int n0 = blockIdx.x * 128;
    const int t  = threadIdx.x;
    const int w  = t >> 5;
    const int lane = t & 31;
    const int g  = lane >> 2;
    const int qd = lane & 3;
    const int row0 = w * 16 + g;

    // X tile [128][64] (rounded)
#pragma unroll
    for (int i = t; i < 128 * 16; i += 256) {
        int r = i >> 4, c4 = (i & 15) << 2;
        float4 v = *(const float4*)&x[(b * N_ + n0 + r) * D_ + h * HD_ + c4];
        v.x = tf32r(v.x); v.y = tf32r(v.y); v.z = tf32r(v.z); v.w = tf32r(v.w);
        *(float4*)&Xs[r * 68 + c4] = v;
    }

    const float* Wm[3] = {Wq, Wk, Wv};
    const float* bm[3] = {bq, bk, bv};
    float*       om[3] = {g_q, g_k, g_v};

    for (int m = 0; m < 3; m++) {
        __syncthreads();
        const float* W = Wm[m] + h * HD_ * HD_;
        // transpose-load W: Ws[e][d] = W[d][e]
#pragma unroll
        for (int i = t; i < 64 * 16; i += 256) {
            int r = i >> 4, c4 = (i & 15) << 2;
            float4 wv = *(const float4*)&W[r * 64 + c4];
            Ws[(c4 + 0) * 68 + r] = tf32r(wv.x);
            Ws[(c4 + 1) * 68 + r] = tf32r(wv.y);
            Ws[(c4 + 2) * 68 + r] = tf32r(wv.z);
            Ws[(c4 + 3) * 68 + r] = tf32r(wv.w);
        }
        __syncthreads();

        const float* bias = bm[m] + h * HD_;
        float acc[8][4];
#pragma unroll
        for (int nt = 0; nt < 8; nt++) {
            float bb0 = bias[nt * 8 + 2 * qd];
            float bb1 = bias[nt * 8 + 2 * qd + 1];
            acc[nt][0] = bb0; acc[nt][1] = bb1; acc[nt][2] = bb0; acc[nt][3] = bb1;
        }

#pragma unroll
        for (int kc = 0; kc < 8; kc++) {
            uint32_t a0 = Xu[(row0)     * 68 + kc * 8 + qd];
            uint32_t a1 = Xu[(row0 + 8) * 68 + kc * 8 + qd];
            uint32_t a2 = Xu[(row0)     * 68 + kc * 8 + qd + 4];
            uint32_t a3 = Xu[(row0 + 8) * 68 + kc * 8 + qd + 4];
#pragma unroll
            for (int nt = 0; nt < 8; nt++) {
                uint32_t b0 = Wu[(nt * 8 + g) * 68 + kc * 8 + qd];
                uint32_t b1 = Wu[(nt * 8 + g) * 68 + kc * 8 + qd + 4];
                mma_tf32(acc[nt], a0, a1, a2, a3, b0, b1);
            }
        }

        float* o = om[m] + ((size_t)bh * N_ + n0) * HD_;
#pragma unroll
        for (int nt = 0; nt < 8; nt++) {
            float2 u0 = make_float2(tf32r(acc[nt][0]), tf32r(acc[nt][1]));
            float2 u1 = make_float2(tf32r(acc[nt][2]), tf32r(acc[nt][3]));
            *(float2*)&o[(row0)     * HD_ + nt * 8 + 2 * qd] = u0;
            *(float2*)&o[(row0 + 8) * HD_ + nt * 8 + 2 * qd] = u1;
        }
    }
}

// ---------------------------------------------------------------------------
// Kernel 2: flash attention with tf32 mma (as R2), output in concat layout.
// K/V already tf32-rounded by qkv kernel (no cvt on load).
// ---------------------------------------------------------------------------
__global__ __launch_bounds__(256, 2) void attn_mma_kernel()
{
    extern __shared__ __align__(16) float sm[];
    float* Qs = sm;                       // [128][68]
    float* Ks = Qs + 128 * 68;            // [64][68]
    float* Ps = Ks + 64 * 68;             // [128][68]
    float* Vs = Ps + 128 * 68;            // [64][72]
    const uint32_t* Qu = (const uint32_t*)Qs;
    const uint32_t* Ku = (const uint32_t*)Ks;
    const uint32_t* Pu = (const uint32_t*)Ps;
    const uint32_t* Vu = (const uint32_t*)Vs;

    const int bh = blockIdx.y;
    const int h  = bh % H_;
    const int b  = bh / H_;
    const int q0 = blockIdx.x * 128;
    const int t  = threadIdx.x;
    const int w  = t >> 5;
    const int lane = t & 31;
    const int g  = lane >> 2;
    const int qd = lane & 3;

    const float scale = rsqrtf((float)D_);   // quirk: full-dim scale
    const float* Qg = g_q + (size_t)bh * N_ * HD_;
    const float* Kg = g_k + (size_t)bh * N_ * HD_;
    const float* Vg = g_v + (size_t)bh * N_ * HD_;

#pragma unroll
    for (int i = t; i < 128 * 16; i += 256) {
        int r = i >> 4, c4 = (i & 15) << 2;
        float4 v = *(const float4*)&Qg[(q0 + r) * HD_ + c4];
        v.x = tf32r(v.x * scale); v.y = tf32r(v.y * scale);
        v.z = tf32r(v.z * scale); v.w = tf32r(v.w * scale);
        *(float4*)&Qs[r * 68 + c4] = v;
    }

    const int row0 = w * 16 + g;

    float O[8][4];
#pragma unroll
    for (int dt = 0; dt < 8; dt++)
#pragma unroll
        for (int j = 0; j < 4; j++) O[dt][j] = 0.f;
    float m0 = -1e30f, m1 = -1e30f, l0 = 0.f, l1 = 0.f;

    for (int kt = 0; kt < N_ / 64; kt++) {
        __syncthreads();
#pragma unroll
        for (int i = t; i < 64 * 16; i += 256) {
            int r = i >> 4, c4 = (i & 15) << 2;
            float4 kv = *(const float4*)&Kg[(kt * 64 + r) * HD_ + c4];
            float4 vv = *(const float4*)&Vg[(kt * 64 + r) * HD_ + c4];
            *(float4*)&Ks[r * 68 + c4] = kv;
            *(float4*)&Vs[r * 72 + c4] = vv;
        }
        __syncthreads();

        float S[8][4];
#pragma unroll
        for (int nt = 0; nt < 8; nt++)
#pragma unroll
            for (int j = 0; j < 4; j++) S[nt][j] = 0.f;

#pragma unroll
        for (int kc = 0; kc < 8; kc++) {
            uint32_t a0 = Qu[(row0)     * 68 + kc * 8 + qd];
            uint32_t a1 = Qu[(row0 + 8) * 68 + kc * 8 + qd];
            uint32_t a2 = Qu[(row0)     * 68 + kc * 8 + qd + 4];
            uint32_t a3 = Qu[(row0 + 8) * 68 + kc * 8 + qd + 4];
#pragma unroll
            for (int nt = 0; nt < 8; nt++) {
                uint32_t b0 = Ku[(nt * 8 + g) * 68 + kc * 8 + qd];
                uint32_t b1 = Ku[(nt * 8 + g) * 68 + kc * 8 + qd + 4];
                mma_tf32(S[nt], a0, a1, a2, a3, b0, b1);
            }
        }

        float mx0 = -1e30f, mx1 = -1e30f;
#pragma unroll
        for (int nt = 0; nt < 8; nt++) {
            mx0 = fmaxf(mx0, fmaxf(S[nt][0], S[nt][1]));
            mx1 = fmaxf(mx1, fmaxf(S[nt][2], S[nt][3]));
        }
        mx0 = fmaxf(mx0, __shfl_xor_sync(0xffffffffu, mx0, 1));
        mx0 = fmaxf(mx0, __shfl_xor_sync(0xffffffffu, mx0, 2));
        mx1 = fmaxf(mx1, __shfl_xor_sync(0xffffffffu, mx1, 1));
        mx1 = fmaxf(mx1, __shfl_xor_sync(0xffffffffu, mx1, 2));

        float nm0 = fmaxf(m0, mx0), nm1 = fmaxf(m1, mx1);
        float corr0 = __expf(m0 - nm0), corr1 = __expf(m1 - nm1);
        m0 = nm0; m1 = nm1;

        float s0 = 0.f, s1 = 0.f;
#pragma unroll
        for (int nt = 0; nt < 8; nt++) {
            S[nt][0] = __expf(S[nt][0] - nm0);
            S[nt][1] = __expf(S[nt][1] - nm0);
            S[nt][2] = __expf(S[nt][2] - nm1);
            S[nt][3] = __expf(S[nt][3] - nm1);
            s0 += S[nt][0] + S[nt][1];
            s1 += S[nt][2] + S[nt][3];
        }
        s0 += __shfl_xor_sync(0xffffffffu, s0, 1);
        s0 += __shfl_xor_sync(0xffffffffu, s0, 2);
        s1 += __shfl_xor_sync(0xffffffffu, s1, 1);
        s1 += __shfl_xor_sync(0xffffffffu, s1, 2);
        l0 = l0 * corr0 + s0;
        l1 = l1 * corr1 + s1;

#pragma unroll
        for (int dt = 0; dt < 8; dt++) {
            O[dt][0] *= corr0; O[dt][1] *= corr0;
            O[dt][2] *= corr1; O[dt][3] *= corr1;
        }

#pragma unroll
        for (int nt = 0; nt < 8; nt++) {
            Ps[(row0)     * 68 + nt * 8 + 2 * qd]     = tf32r(S[nt][0]);
            Ps[(row0)     * 68 + nt * 8 + 2 * qd + 1] = tf32r(S[nt][1]);
            Ps[(row0 + 8) * 68 + nt * 8 + 2 * qd]     = tf32r(S[nt][2]);
            Ps[(row0 + 8) * 68 + nt * 8 + 2 * qd + 1] = tf32r(S[nt][3]);
        }
        __syncwarp();

#pragma unroll
        for (int kc = 0; kc < 8; kc++) {
            uint32_t a0 = Pu[(row0)     * 68 + kc * 8 + qd];
            uint32_t a1 = Pu[(row0 + 8) * 68 + kc * 8 + qd];
            uint32_t a2 = Pu[(row0)     * 68 + kc * 8 + qd + 4];
            uint32_t a3 = Pu[(row0 + 8) * 68 + kc * 8 + qd + 4];
#pragma unroll
            for (int dt = 0; dt < 8; dt++) {
                uint32_t b0 = Vu[(kc * 8 + qd)     * 72 + dt * 8 + g];
                uint32_t b1 = Vu[(kc * 8 + qd + 4) * 72 + dt * 8 + g];
                mma_tf32(O[dt], a0, a1, a2, a3, b0, b1);
            }
        }
        __syncwarp();
    }

    // normalize + store in concat layout [B*N, D]
    float inv0 = 1.f / l0, inv1 = 1.f / l1;
    float* Ao = g_att + ((size_t)b * N_ + q0) * D_ + h * HD_;
#pragma unroll
    for (int dt = 0; dt < 8; dt++) {
        float2 u0 = make_float2(O[dt][0] * inv0, O[dt][1] * inv0);
        float2 u1 = make_float2(O[dt][2] * inv1, O[dt][3] * inv1);
        *(float2*)&Ao[(size_t)(row0)     * D_ + dt * 8 + 2 * qd] = u0;
        *(float2*)&Ao[(size_t)(row0 + 8) * D_ + dt * 8 + 2 * qd] = u1;
    }
}

// ---------------------------------------------------------------------------
// Kernel 3: output projection, tf32 mma.
// out[r, c] = sum_k A[r,k] * Wo[c,k] + bo[c]; A = g_att (concat layout).
// grid (12, 64) = (col tile 64, row tile 128). block 256 = 8 warps.
// ---------------------------------------------------------------------------
__global__ __launch_bounds__(256) void outproj_mma_kernel(
    const float* __restrict__ Wo, const float* __restrict__ bo,
    float* __restrict__ out)
{
    extern __shared__ __align__(16) float sm[];
    float* As = sm;               // [128][68]
    float* Ws = As + 128 * 68;    // [64][68]  Ws[c][kk]
    const uint32_t* Au = (const uint32_t*)As;
    const uint32_t* Wu = (const uint32_t*)Ws;

    const int c0 = blockIdx.x * 64;
    const int r0 = blockIdx.y * 128;
    const int t  = threadIdx.x;
    const int w  = t >> 5;
    const int lane = t & 31;
    const int g  = lane >> 2;
    const int qd = lane & 3;
    const int row0 = w * 16 + g;

    float acc[8][4];
#pragma unroll
    for (int nt = 0; nt < 8; nt++) {
        float bb0 = bo[c0 + nt * 8 + 2 * qd];
        float bb1 = bo[c0 + nt * 8 + 2 * qd + 1];
        acc[nt][0] = bb0; acc[nt][1] = bb1; acc[nt][2] = bb0; acc[nt][3] = bb1;
    }

    for (int kt = 0; kt < D_ / 64; kt++) {
        __syncthreads();
        // A tile [128][64]
#pragma unroll
        for (int i = t; i < 128 * 16; i += 256) {
            int r = i >> 4, c4 = (i & 15) << 2;
            float4 v = *(const float4*)&g_att[(size_t)(r0 + r) * D_ + kt * 64 + c4];
            v.x = tf32r(v.x); v.y = tf32r(v.y); v.z = tf32r(v.z); v.w = tf32r(v.w);
            *(float4*)&As[r * 68 + c4] = v;
        }
        // W tile: Ws[c][kk] = Wo[c0+c][kt*64+kk]  (kk contiguous)
#pragma unroll
        for (int i = t; i < 64 * 16; i += 256) {
            int r = i >> 4, c4 = (i & 15) << 2;
            float4 v = *(const float4*)&Wo[(size_t)(c0 + r) * D_ + kt * 64 + c4];
            v.x = tf32r(v.x); v.y = tf32r(v.y); v.z = tf32r(v.z); v.w = tf32r(v.w);
            *(float4*)&Ws[r * 68 + c4] = v;
        }
        __syncthreads();

#pragma unroll
        for (int kc = 0; kc < 8; kc++) {
            uint32_t a0 = Au[(row0)     * 68 + kc * 8 + qd];
            uint32_t a1 = Au[(row0 + 8) * 68 + kc * 8 + qd];
            uint32_t a2 = Au[(row0)     * 68 + kc * 8 + qd + 4];
            uint32_t a3 = Au[(row0 + 8) * 68 + kc * 8 + qd + 4];
#pragma unroll
            for (int nt = 0; nt < 8; nt++) {
                uint32_t b0 = Wu[(nt * 8 + g) * 68 + kc * 8 + qd];
                uint32_t b1 = Wu[(nt * 8 + g) * 68 + kc * 8 + qd + 4];
                mma_tf32(acc[nt], a0, a1, a2, a3, b0, b1);
            }
        }
    }

#pragma unroll
    for (int nt = 0; nt < 8; nt++) {
        float2 u0 = make_float2(acc[nt][0], acc[nt][1]);
        float2 u1 = make_float2(acc[nt][2], acc[nt][3]);
        *(float2*)&out[(size_t)(r0 + row0)     * D_ + c0 + nt * 8 + 2 * qd] = u0;
        *(float2*)&out[(size_t)(r0 + row0 + 8) * D_ + c0 + nt * 8 + 2 * qd] = u1;
    }
}

// ---------------------------------------------------------------------------
extern "C" void kernel_launch(void* const* d_in, const int* in_sizes, int n_in,
                              void* d_out, int out_size)
{
    const float* x  = (const float*)d_in[0];
    const float* Wq = (const float*)d_in[1];
    const float* Wk = (const float*)d_in[2];
    const float* Wv = (const float*)d_in[3];
    const float* bq = (const float*)d_in[4];
    const float* bk = (const float*)d_in[5];
    const float* bv = (const float*)d_in[6];
    const float* Wo = (const float*)d_in[7];
    const float* bo = (const float*)d_in[8];
    float* out = (float*)d_out;

    const int proj_smem = (128 * 68 + 64 * 68) * (int)sizeof(float);                      // 52224
    const int attn_smem = (128 * 68 + 64 * 68 + 128 * 68 + 64 * 72) * (int)sizeof(float); // 105472
    cudaFuncSetAttribute(qkv_mma_kernel, cudaFuncAttributeMaxDynamicSharedMemorySize, proj_smem);
    cudaFuncSetAttribute(attn_mma_kernel, cudaFuncAttributeMaxDynamicSharedMemorySize, attn_smem);
    cudaFuncSetAttribute(outproj_mma_kernel, cudaFuncAttributeMaxDynamicSharedMemorySize, proj_smem);

    qkv_mma_kernel<<<dim3(N_ / 128, B_ * H_), 256, proj_smem>>>(x, Wq, Wk, Wv, bq, bk, bv);
    attn_mma_kernel<<<dim3(N_ / 128, B_ * H_), 256, attn_smem>>>();
    outproj_mma_kernel<<<dim3(D_ / 64, (B_ * N_) / 128), 256, proj_smem>>>(Wo, bo, out);
}

// round 4
// speedup vs baseline: 3.4623x; 1.2798x over previous
#include <cuda_runtime.h>
#include <cuda_fp16.h>
#include <cstdint>

#define B_ 8
#define N_ 1024
#define D_ 768
#define H_ 12
#define HD_ 64

// Scratch (allocation-free rule: __device__ globals)
__device__ float g_q[B_ * H_ * N_ * HD_];
__device__ float g_k[B_ * H_ * N_ * HD_];
__device__ float g_v[B_ * H_ * N_ * HD_];
__device__ float g_att[B_ * N_ * D_];   // concat layout [B*N, D]

// ---------------------------------------------------------------------------
// helpers
// ---------------------------------------------------------------------------
__device__ __forceinline__ float tf32r(float x) {
    uint32_t u;
    asm("cvt.rna.tf32.f32 %0, %1;" : "=r"(u) : "f"(x));
    return __uint_as_float(u);
}

__device__ __forceinline__ float ex2f(float x) {
    float y;
    asm("ex2.approx.ftz.f32 %0, %1;" : "=f"(y) : "f"(x));
    return y;
}

__device__ __forceinline__ void mma_tf32(float c[4],
                                         uint32_t a0, uint32_t a1, uint32_t a2, uint32_t a3,
                                         uint32_t b0, uint32_t b1) {
    asm volatile(
        "mma.sync.aligned.m16n8k8.row.col.f32.tf32.tf32.f32 "
        "{%0,%1,%2,%3},{%4,%5,%6,%7},{%8,%9},{%0,%1,%2,%3};\n"
        : "+f"(c[0]), "+f"(c[1]), "+f"(c[2]), "+f"(c[3])
        : "r"(a0), "r"(a1), "r"(a2), "r"(a3), "r"(b0), "r"(b1));
}

__device__ __forceinline__ void mma_f16(float c[4],
                                        uint32_t a0, uint32_t a1, uint32_t a2, uint32_t a3,
                                        uint32_t b0, uint32_t b1) {
    asm volatile(
        "mma.sync.aligned.m16n8k16.row.col.f32.f16.f16.f32 "
        "{%0,%1,%2,%3},{%4,%5,%6,%7},{%8,%9},{%0,%1,%2,%3};\n"
        : "+f"(c[0]), "+f"(c[1]), "+f"(c[2]), "+f"(c[3])
        : "r"(a0), "r"(a1), "r"(a2), "r"(a3), "r"(b0), "r"(b1));
}

__device__ __forceinline__ uint32_t packh2(float lo, float hi) {
    __half2 h = __floats2half2_rn(lo, hi);
    return *(uint32_t*)&h;
}

// ---------------------------------------------------------------------------
// Kernel 1: per-head QKV projection, tf32 mma.
// grid (8, 96). block 256 = 8 warps. X frags hoisted, reused for q/k/v.
// Xs pair-permuted (stride 72); Ws direct copy [d][e] (stride 72).
// ---------------------------------------------------------------------------
__global__ __launch_bounds__(256) void qkv_mma_kernel(
    const float* __restrict__ x,
    const float* __restrict__ Wq, const float* __restrict__ Wk, const float* __restrict__ Wv,
    const float* __restrict__ bq, const float* __restrict__ bk, const float* __restrict__ bv)
{
    extern __shared__ __align__(16) float sm[];
    float* Xs = sm;               // [128][72] pair-permuted cols
    float* Ws = Xs + 128 * 72;    // [64][72]  Ws[d][e] direct

    const int bh = blockIdx.y;
    const int h  = bh % H_;
    const int b  = bh / H_;
    const int n0 = blockIdx.x * 128;
    const int t  = threadIdx.x;
    const int w  = t >> 5;
    const int lane = t & 31;
    const int g  = lane >> 2;
    const int qd = lane & 3;
    const int row0 = w * 16 + g;

    // X tile: pair-permuted store (cols d, d+4 adjacent), tf32-rounded
#pragma unroll
    for (int i = t; i < 128 * 8; i += 256) {
        int r = i >> 3, c8 = (i & 7) << 3;
        const float* src = &x[(b * N_ + n0 + r) * D_ + h * HD_ + c8];
        float4 v0 = *(const float4*)src;
        float4 v1 = *(const float4*)(src + 4);
        float* dst = &Xs[r * 72 + c8];
        *(float2*)(dst + 0) = make_float2(tf32r(v0.x), tf32r(v1.x));
        *(float2*)(dst + 2) = make_float2(tf32r(v0.y), tf32r(v1.y));
        *(float2*)(dst + 4) = make_float2(tf32r(v0.z), tf32r(v1.z));
        *(float2*)(dst + 6) = make_float2(tf32r(v0.w), tf32r(v1.w));
    }
    __syncthreads();

    // hoist X fragments: 8 kc x (two rows) float2
    float2 xa[8], xb[8];
#pragma unroll
    for (int kc = 0; kc < 8; kc++) {
        xa[kc] = *(const float2*)&Xs[(row0)     * 72 + kc * 8 + 2 * qd];
        xb[kc] = *(const float2*)&Xs[(row0 + 8) * 72 + kc * 8 + 2 * qd];
    }

    const float* Wm[3] = {Wq, Wk, Wv};
    const float* bm[3] = {bq, bk, bv};
    float*       om[3] = {g_q, g_k, g_v};

    for (int m = 0; m < 3; m++) {
        __syncthreads();
        const float* W = Wm[m] + h * HD_ * HD_;
#pragma unroll
        for (int i = t; i < 64 * 16; i += 256) {
            int r = i >> 4, c4 = (i & 15) << 2;
            float4 v = *(const float4*)&W[r * 64 + c4];
            v.x = tf32r(v.x); v.y = tf32r(v.y); v.z = tf32r(v.z); v.w = tf32r(v.w);
            *(float4*)&Ws[r * 72 + c4] = v;
        }
        __syncthreads();

        const float* bias = bm[m] + h * HD_;
        float acc[8][4];
#pragma unroll
        for (int nt = 0; nt < 8; nt++) {
            float bb0 = bias[nt * 8 + 2 * qd];
            float bb1 = bias[nt * 8 + 2 * qd + 1];
            acc[nt][0] = bb0; acc[nt][1] = bb1; acc[nt][2] = bb0; acc[nt][3] = bb1;
        }

#pragma unroll
        for (int kc = 0; kc < 8; kc++) {
            uint32_t a0 = __float_as_uint(xa[kc].x);
            uint32_t a1 = __float_as_uint(xb[kc].x);
            uint32_t a2 = __float_as_uint(xa[kc].y);
            uint32_t a3 = __float_as_uint(xb[kc].y);
#pragma unroll
            for (int nt = 0; nt < 8; nt++) {
                uint32_t b0 = __float_as_uint(Ws[(kc * 8 + qd)     * 72 + nt * 8 + g]);
                uint32_t b1 = __float_as_uint(Ws[(kc * 8 + qd + 4) * 72 + nt * 8 + g]);
                mma_tf32(acc[nt], a0, a1, a2, a3, b0, b1);
            }
        }

        float* o = om[m] + ((size_t)bh * N_ + n0) * HD_;
#pragma unroll
        for (int nt = 0; nt < 8; nt++) {
            float2 u0 = make_float2(tf32r(acc[nt][0]), tf32r(acc[nt][1]));
            float2 u1 = make_float2(tf32r(acc[nt][2]), tf32r(acc[nt][3]));
            *(float2*)&o[(row0)     * HD_ + nt * 8 + 2 * qd] = u0;
            *(float2*)&o[(row0 + 8) * HD_ + nt * 8 + 2 * qd] = u1;
        }
    }
}

// ---------------------------------------------------------------------------
// Kernel 2: flash attention. S via tf32 mma (Q frags hoisted, K pair-perm);
// P kept in registers as fp16, PV via fp16 m16n8k16 (V packed f16x2 in smem).
// Softmax in log2 domain (ex2), scale*log2e folded into Q.
// ---------------------------------------------------------------------------
__global__ __launch_bounds__(256, 2) void attn_mma_kernel()
{
    extern __shared__ __align__(16) float sm[];
    float* Qs = sm;                       // [128][72] pair-permuted
    float* Ks = Qs + 128 * 72;            // [64][72]  pair-permuted
    uint32_t* Vp = (uint32_t*)(Ks + 64 * 72);  // [32][72] f16x2, packs key-pairs

    const int bh = blockIdx.y;
    const int h  = bh % H_;
    const int b  = bh / H_;
    const int q0 = blockIdx.x * 128;
    const int t  = threadIdx.x;
    const int w  = t >> 5;
    const int lane = t & 31;
    const int g  = lane >> 2;
    const int qd = lane & 3;
    const int row0 = w * 16 + g;

    const float scale2 = rsqrtf((float)D_) * 1.4426950408889634f;  // full-dim quirk * log2e
    const float* Qg = g_q + (size_t)bh * N_ * HD_;
    const float* Kg = g_k + (size_t)bh * N_ * HD_;
    const float* Vg = g_v + (size_t)bh * N_ * HD_;

    // Q tile: scale + round + pair-permute
#pragma unroll
    for (int i = t; i < 128 * 8; i += 256) {
        int r = i >> 3, c8 = (i & 7) << 3;
        const float* src = &Qg[(q0 + r) * HD_ + c8];
        float4 v0 = *(const float4*)src;
        float4 v1 = *(const float4*)(src + 4);
        float* dst = &Qs[r * 72 + c8];
        *(float2*)(dst + 0) = make_float2(tf32r(v0.x * scale2), tf32r(v1.x * scale2));
        *(float2*)(dst + 2) = make_float2(tf32r(v0.y * scale2), tf32r(v1.y * scale2));
        *(float2*)(dst + 4) = make_float2(tf32r(v0.z * scale2), tf32r(v1.z * scale2));
        *(float2*)(dst + 6) = make_float2(tf32r(v0.w * scale2), tf32r(v1.w * scale2));
    }
    // K tile kt=0: pair-permute (already tf32-rounded by qkv)
#pragma unroll
    for (int i = t; i < 64 * 8; i += 256) {
        int r = i >> 3, c8 = (i & 7) << 3;
        const float* src = &Kg[r * HD_ + c8];
        float4 v0 = *(const float4*)src;
        float4 v1 = *(const float4*)(src + 4);
        float* dst = &Ks[r * 72 + c8];
        *(float2*)(dst + 0) = make_float2(v0.x, v1.x);
        *(float2*)(dst + 2) = make_float2(v0.y, v1.y);
        *(float2*)(dst + 4) = make_float2(v0.z, v1.z);
        *(float2*)(dst + 6) = make_float2(v0.w, v1.w);
    }
    // V tile kt=0: pack key-pairs to f16x2
#pragma unroll
    for (int i = t; i < 32 * 16; i += 256) {
        int r2 = i >> 4, c4 = (i & 15) << 2;
        float4 a = *(const float4*)&Vg[(2 * r2)     * HD_ + c4];
        float4 bb = *(const float4*)&Vg[(2 * r2 + 1) * HD_ + c4];
        uint4 wv;
        wv.x = packh2(a.x, bb.x); wv.y = packh2(a.y, bb.y);
        wv.z = packh2(a.z, bb.z); wv.w = packh2(a.w, bb.w);
        *(uint4*)&Vp[r2 * 72 + c4] = wv;
    }
    __syncthreads();

    // hoist Q fragments
    float2 qa[8], qb[8];
#pragma unroll
    for (int kc = 0; kc < 8; kc++) {
        qa[kc] = *(const float2*)&Qs[(row0)     * 72 + kc * 8 + 2 * qd];
        qb[kc] = *(const float2*)&Qs[(row0 + 8) * 72 + kc * 8 + 2 * qd];
    }

    float O[8][4];
#pragma unroll
    for (int dt = 0; dt < 8; dt++)
#pragma unroll
        for (int j = 0; j < 4; j++) O[dt][j] = 0.f;
    float m0 = -1e30f, m1 = -1e30f, l0 = 0.f, l1 = 0.f;

    for (int kt = 0; kt < N_ / 64; kt++) {
        // ---- S = Q K^T ----
        float S[8][4];
#pragma unroll
        for (int nt = 0; nt < 8; nt++)
#pragma unroll
            for (int j = 0; j < 4; j++) S[nt][j] = 0.f;

#pragma unroll
        for (int kc = 0; kc < 8; kc++) {
            uint32_t a0 = __float_as_uint(qa[kc].x);
            uint32_t a1 = __float_as_uint(qb[kc].x);
            uint32_t a2 = __float_as_uint(qa[kc].y);
            uint32_t a3 = __float_as_uint(qb[kc].y);
#pragma unroll
            for (int nt = 0; nt < 8; nt++) {
                float2 kb = *(const float2*)&Ks[(nt * 8 + g) * 72 + kc * 8 + 2 * qd];
                mma_tf32(S[nt], a0, a1, a2, a3,
                         __float_as_uint(kb.x), __float_as_uint(kb.y));
            }
        }

        // ---- online softmax in log2 domain ----
        float mx0 = -1e30f, mx1 = -1e30f;
#pragma unroll
        for (int nt = 0; nt < 8; nt++) {
            mx0 = fmaxf(mx0, fmaxf(S[nt][0], S[nt][1]));
            mx1 = fmaxf(mx1, fmaxf(S[nt][2], S[nt][3]));
        }
        mx0 = fmaxf(mx0, __shfl_xor_sync(0xffffffffu, mx0, 1));
        mx0 = fmaxf(mx0, __shfl_xor_sync(0xffffffffu, mx0, 2));
        mx1 = fmaxf(mx1, __shfl_xor_sync(0xffffffffu, mx1, 1));
        mx1 = fmaxf(mx1, __shfl_xor_sync(0xffffffffu, mx1, 2));

        float nm0 = fmaxf(m0, mx0), nm1 = fmaxf(m1, mx1);
        float corr0 = ex2f(m0 - nm0), corr1 = ex2f(m1 - nm1);
        m0 = nm0; m1 = nm1;

        float s0 = 0.f, s1 = 0.f;
#pragma unroll
        for (int nt = 0; nt < 8; nt++) {
            S[nt][0] = ex2f(S[nt][0] - nm0);
            S[nt][1] = ex2f(S[nt][1] - nm0);
            S[nt][2] = ex2f(S[nt][2] - nm1);
            S[nt][3] = ex2f(S[nt][3] - nm1);
            s0 += S[nt][0] + S[nt][1];
            s1 += S[nt][2] + S[nt][3];
        }
        s0 += __shfl_xor_sync(0xffffffffu, s0, 1);
        s0 += __shfl_xor_sync(0xffffffffu, s0, 2);
        s1 += __shfl_xor_sync(0xffffffffu, s1, 1);
        s1 += __shfl_xor_sync(0xffffffffu, s1, 2);
        l0 = l0 * corr0 + s0;
        l1 = l1 * corr1 + s1;

#pragma unroll
        for (int dt = 0; dt < 8; dt++) {
            O[dt][0] *= corr0; O[dt][1] *= corr0;
            O[dt][2] *= corr1; O[dt][3] *= corr1;
        }

        // ---- P (registers, fp16) : O += P V ----
#pragma unroll
        for (int c = 0; c < 4; c++) {
            uint32_t a0 = packh2(S[2 * c][0],     S[2 * c][1]);
            uint32_t a1 = packh2(S[2 * c][2],     S[2 * c][3]);
            uint32_t a2 = packh2(S[2 * c + 1][0], S[2 * c + 1][1]);
            uint32_t a3 = packh2(S[2 * c + 1][2], S[2 * c + 1][3]);
#pragma unroll
            for (int dt = 0; dt < 8; dt++) {
                uint32_t b0 = Vp[(8 * c + qd)     * 72 + dt * 8 + g];
                uint32_t b1 = Vp[(8 * c + 4 + qd) * 72 + dt * 8 + g];
                mma_f16(O[dt], a0, a1, a2, a3, b0, b1);
            }
        }

        // ---- load next K/V tile ----
        if (kt + 1 < N_ / 64) {
            __syncthreads();
            const float* Kn = Kg + (kt + 1) * 64 * HD_;
            const float* Vn = Vg + (kt + 1) * 64 * HD_;
#pragma unroll
            for (int i = t; i < 64 * 8; i += 256) {
                int r = i >> 3, c8 = (i & 7) << 3;
                const float* src = &Kn[r * HD_ + c8];
                float4 v0 = *(const float4*)src;
                float4 v1 = *(const float4*)(src + 4);
                float* dst = &Ks[r * 72 + c8];
                *(float2*)(dst + 0) = make_float2(v0.x, v1.x);
                *(float2*)(dst + 2) = make_float2(v0.y, v1.y);
                *(float2*)(dst + 4) = make_float2(v0.z, v1.z);
                *(float2*)(dst + 6) = make_float2(v0.w, v1.w);
            }
#pragma unroll
            for (int i = t; i < 32 * 16; i += 256) {
                int r2 = i >> 4, c4 = (i & 15) << 2;
                float4 a = *(const float4*)&Vn[(2 * r2)     * HD_ + c4];
                float4 bb = *(const float4*)&Vn[(2 * r2 + 1) * HD_ + c4];
                uint4 wv;
                wv.x = packh2(a.x, bb.x); wv.y = packh2(a.y, bb.y);
                wv.z = packh2(a.z, bb.z); wv.w = packh2(a.w, bb.w);
                *(uint4*)&Vp[r2 * 72 + c4] = wv;
            }
            __syncthreads();
        }
    }

    // normalize + store in concat layout [B*N, D]
    float inv0 = 1.f / l0, inv1 = 1.f / l1;
    float* Ao = g_att + ((size_t)b * N_ + q0) * D_ + h * HD_;
#pragma unroll
    for (int dt = 0; dt < 8; dt++) {
        float2 u0 = make_float2(O[dt][0] * inv0, O[dt][1] * inv0);
        float2 u1 = make_float2(O[dt][2] * inv1, O[dt][3] * inv1);
        *(float2*)&Ao[(size_t)(row0)     * D_ + dt * 8 + 2 * qd] = u0;
        *(float2*)&Ao[(size_t)(row0 + 8) * D_ + dt * 8 + 2 * qd] = u1;
    }
}

// ---------------------------------------------------------------------------
// Kernel 3: output projection, tf32 mma, pair-permuted tiles.
// out[r, c] = sum_k A[r,k] * Wo[c,k] + bo[c]
// ---------------------------------------------------------------------------
__global__ __launch_bounds__(256) void outproj_mma_kernel(
    const float* __restrict__ Wo, const float* __restrict__ bo,
    float* __restrict__ out)
{
    extern __shared__ __align__(16) float sm[];
    float* As = sm;               // [128][72] pair-permuted
    float* Ws = As + 128 * 72;    // [64][72]  pair-permuted rows of Wo

    const int c0 = blockIdx.x * 64;
    const int r0 = blockIdx.y * 128;
    const int t  = threadIdx.x;
    const int w  = t >> 5;
    const int lane = t & 31;
    const int g  = lane >> 2;
    const int qd = lane & 3;
    const int row0 = w * 16 + g;

    float acc[8][4];
#pragma unroll
    for (int nt = 0; nt < 8; nt++) {
        float bb0 = bo[c0 + nt * 8 + 2 * qd];
        float bb1 = bo[c0 + nt * 8 + 2 * qd + 1];
        acc[nt][0] = bb0; acc[nt][1] = bb1; acc[nt][2] = bb0; acc[nt][3] = bb1;
    }

    for (int kt = 0; kt < D_ / 64; kt++) {
        __syncthreads();
#pragma unroll
        for (int i = t; i < 128 * 8; i += 256) {
            int r = i >> 3, c8 = (i & 7) << 3;
            const float* src = &g_att[(size_t)(r0 + r) * D_ + kt * 64 + c8];
            float4 v0 = *(const float4*)src;
            float4 v1 = *(const float4*)(src + 4);
            float* dst = &As[r * 72 + c8];
            *(float2*)(dst + 0) = make_float2(tf32r(v0.x), tf32r(v1.x));
            *(float2*)(dst + 2) = make_float2(tf32r(v0.y), tf32r(v1.y));
            *(float2*)(dst + 4) = make_float2(tf32r(v0.z), tf32r(v1.z));
            *(float2*)(dst + 6) = make_float2(tf32r(v0.w), tf32r(v1.w));
        }
#pragma unroll
        for (int i = t; i < 64 * 8; i += 256) {
            int r = i >> 3, c8 = (i & 7) << 3;
            const float* src = &Wo[(size_t)(c0 + r) * D_ + kt * 64 + c8];
            float4 v0 = *(const float4*)src;
            float4 v1 = *(const float4*)(src + 4);
            float* dst = &Ws[r * 72 + c8];
            *(float2*)(dst + 0) = make_float2(tf32r(v0.x), tf32r(v1.x));
            *(float2*)(dst + 2) = make_float2(tf32r(v0.y), tf32r(v1.y));
            *(float2*)(dst + 4) = make_float2(tf32r(v0.z), tf32r(v1.z));
            *(float2*)(dst + 6) = make_float2(tf32r(v0.w), tf32r(v1.w));
        }
        __syncthreads();

#pragma unroll
        for (int kc = 0; kc < 8; kc++) {
            float2 aa = *(const float2*)&As[(row0)     * 72 + kc * 8 + 2 * qd];
            float2 ab = *(const float2*)&As[(row0 + 8) * 72 + kc * 8 + 2 * qd];
            uint32_t a0 = __float_as_uint(aa.x);
            uint32_t a1 = __float_as_uint(ab.x);
            uint32_t a2 = __float_as_uint(aa.y);
            uint32_t a3 = __float_as_uint(ab.y);
#pragma unroll
            for (int nt = 0; nt < 8; nt++) {
                float2 wb = *(const float2*)&Ws[(nt * 8 + g) * 72 + kc * 8 + 2 * qd];
                mma_tf32(acc[nt], a0, a1, a2, a3,
                         __float_as_uint(wb.x), __float_as_uint(wb.y));
            }
        }
    }

#pragma unroll
    for (int nt = 0; nt < 8; nt++) {
        float2 u0 = make_float2(acc[nt][0], acc[nt][1]);
        float2 u1 = make_float2(acc[nt][2], acc[nt][3]);
        *(float2*)&out[(size_t)(r0 + row0)     * D_ + c0 + nt * 8 + 2 * qd] = u0;
        *(float2*)&out[(size_t)(r0 + row0 + 8) * D_ + c0 + nt * 8 + 2 * qd] = u1;
    }
}

// ---------------------------------------------------------------------------
extern "C" void kernel_launch(void* const* d_in, const int* in_sizes, int n_in,
                              void* d_out, int out_size)
{
    const float* x  = (const float*)d_in[0];
    const float* Wq = (const float*)d_in[1];
    const float* Wk = (const float*)d_in[2];
    const float* Wv = (const float*)d_in[3];
    const float* bq = (const float*)d_in[4];
    const float* bk = (const float*)d_in[5];
    const float* bv = (const float*)d_in[6];
    const float* Wo = (const float*)d_in[7];
    const float* bo = (const float*)d_in[8];
    float* out = (float*)d_out;

    const int proj_smem = (128 * 72 + 64 * 72) * (int)sizeof(float);              // 55296
    const int attn_smem = (128 * 72 + 64 * 72 + 32 * 72) * (int)sizeof(float);    // 64512
    cudaFuncSetAttribute(qkv_mma_kernel, cudaFuncAttributeMaxDynamicSharedMemorySize, proj_smem);
    cudaFuncSetAttribute(attn_mma_kernel, cudaFuncAttributeMaxDynamicSharedMemorySize, attn_smem);
    cudaFuncSetAttribute(outproj_mma_kernel, cudaFuncAttributeMaxDynamicSharedMemorySize, proj_smem);

    qkv_mma_kernel<<<dim3(N_ / 128, B_ * H_), 256, proj_smem>>>(x, Wq, Wk, Wv, bq, bk, bv);
    attn_mma_kernel<<<dim3(N_ / 128, B_ * H_), 256, attn_smem>>>();
    outproj_mma_kernel<<<dim3(D_ / 64, (B_ * N_) / 128), 256, proj_smem>>>(Wo, bo, out);
}

// round 5
// speedup vs baseline: 5.6376x; 1.6283x over previous
#include <cuda_runtime.h>
#include <cuda_fp16.h>
#include <cstdint>

#define B_ 8
#define N_ 1024
#define D_ 768
#define H_ 12
#define HD_ 64

// Scratch (allocation-free rule: __device__ globals) — fp16 intermediates
__device__ __half g_q[B_ * H_ * N_ * HD_];   // pre-scaled by D^-0.5 * log2e
__device__ __half g_k[B_ * H_ * N_ * HD_];
__device__ __half g_v[B_ * H_ * N_ * HD_];
__device__ __half g_att[B_ * N_ * D_];       // concat layout [B*N, D]

// ---------------------------------------------------------------------------
// helpers
// ---------------------------------------------------------------------------
__device__ __forceinline__ float ex2f(float x) {
    float y;
    asm("ex2.approx.ftz.f32 %0, %1;" : "=f"(y) : "f"(x));
    return y;
}

__device__ __forceinline__ void mma_f16(float c[4],
                                        uint32_t a0, uint32_t a1, uint32_t a2, uint32_t a3,
                                        uint32_t b0, uint32_t b1) {
    asm volatile(
        "mma.sync.aligned.m16n8k16.row.col.f32.f16.f16.f32 "
        "{%0,%1,%2,%3},{%4,%5,%6,%7},{%8,%9},{%0,%1,%2,%3};\n"
        : "+f"(c[0]), "+f"(c[1]), "+f"(c[2]), "+f"(c[3])
        : "r"(a0), "r"(a1), "r"(a2), "r"(a3), "r"(b0), "r"(b1));
}

__device__ __forceinline__ uint32_t packh2(float lo, float hi) {
    __half2 h = __floats2half2_rn(lo, hi);
    return *(uint32_t*)&h;
}

// ---------------------------------------------------------------------------
// Kernel 1: per-head QKV projection, fp16 mma (fp32 accum).
// grid (8, 96). block 256 = 8 warps. X frags hoisted, reused for q/k/v.
// Xs: [128][36] half2 (k-pairs natural).  Ws: [e][36] half2 packed along d.
// Q output pre-scaled by D^-0.5*log2e.
// ---------------------------------------------------------------------------
__global__ __launch_bounds__(256) void qkv_mma_kernel(
    const float* __restrict__ x,
    const float* __restrict__ Wq, const float* __restrict__ Wk, const float* __restrict__ Wv,
    const float* __restrict__ bq, const float* __restrict__ bk, const float* __restrict__ bv)
{
    extern __shared__ __align__(16) uint32_t smu[];
    uint32_t* Xs = smu;              // 128*36 half2
    uint32_t* Ws = Xs + 128 * 36;    // 64*36  half2  (Ws[e][d2])

    const int bh = blockIdx.y;
    const int h  = bh % H_;
    const int b  = bh / H_;
    const int n0 = blockIdx.x * 128;
    const int t  = threadIdx.x;
    const int w  = t >> 5;
    const int lane = t & 31;
    const int g  = lane >> 2;
    const int qd = lane & 3;
    const int row0 = w * 16 + g;

    // X tile: fp32 -> half2 (natural k-pairs)
#pragma unroll
    for (int i = t; i < 128 * 8; i += 256) {
        int r = i >> 3, c8 = (i & 7) << 3;   // 8 floats per unit
        const float* src = &x[(b * N_ + n0 + r) * D_ + h * HD_ + c8];
        float4 v0 = *(const float4*)src;
        float4 v1 = *(const float4*)(src + 4);
        uint4 pk;
        pk.x = packh2(v0.x, v0.y); pk.y = packh2(v0.z, v0.w);
        pk.z = packh2(v1.x, v1.y); pk.w = packh2(v1.z, v1.w);
        *(uint4*)&Xs[r * 36 + (c8 >> 1)] = pk;
    }
    __syncthreads();

    // hoist X fragments: 4 k16 chunks x {a0,a1,a2,a3}
    uint32_t xa[4][4];
#pragma unroll
    for (int kc = 0; kc < 4; kc++) {
        xa[kc][0] = Xs[(row0)     * 36 + kc * 8 + qd];
        xa[kc][1] = Xs[(row0 + 8) * 36 + kc * 8 + qd];
        xa[kc][2] = Xs[(row0)     * 36 + kc * 8 + qd + 4];
        xa[kc][3] = Xs[(row0 + 8) * 36 + kc * 8 + qd + 4];
    }

    const float* Wm[3] = {Wq, Wk, Wv};
    const float* bm[3] = {bq, bk, bv};
    __half*      om[3] = {g_q, g_k, g_v};
    const float qscale = rsqrtf((float)D_) * 1.4426950408889634f;  // full-dim quirk * log2e

    for (int m = 0; m < 3; m++) {
        __syncthreads();
        const float* W = Wm[m] + h * HD_ * HD_;
        __half* Wh = (__half*)Ws;
        // coalesced fp32 read, scattered 2B smem writes: Wh[e][d] with row stride 72 halfs
#pragma unroll
        for (int i = t; i < 64 * 16; i += 256) {
            int r = i >> 4, c4 = (i & 15) << 2;   // r = d, c4 = e
            float4 v = *(const float4*)&W[r * 64 + c4];
            Wh[(c4 + 0) * 72 + r] = __float2half(v.x);
            Wh[(c4 + 1) * 72 + r] = __float2half(v.y);
            Wh[(c4 + 2) * 72 + r] = __float2half(v.z);
            Wh[(c4 + 3) * 72 + r] = __float2half(v.w);
        }
        __syncthreads();

        const float* bias = bm[m] + h * HD_;
        float acc[8][4];
#pragma unroll
        for (int nt = 0; nt < 8; nt++) {
            float bb0 = bias[nt * 8 + 2 * qd];
            float bb1 = bias[nt * 8 + 2 * qd + 1];
            acc[nt][0] = bb0; acc[nt][1] = bb1; acc[nt][2] = bb0; acc[nt][3] = bb1;
        }

#pragma unroll
        for (int kc = 0; kc < 4; kc++) {
#pragma unroll
            for (int nt = 0; nt < 8; nt++) {
                uint32_t b0 = Ws[(nt * 8 + g) * 36 + kc * 8 + qd];
                uint32_t b1 = Ws[(nt * 8 + g) * 36 + kc * 8 + qd + 4];
                mma_f16(acc[nt], xa[kc][0], xa[kc][1], xa[kc][2], xa[kc][3], b0, b1);
            }
        }

        const float sc = (m == 0) ? qscale : 1.0f;
        __half* o = om[m] + ((size_t)bh * N_ + n0) * HD_;
#pragma unroll
        for (int nt = 0; nt < 8; nt++) {
            *(uint32_t*)&o[(row0)     * HD_ + nt * 8 + 2 * qd] = packh2(acc[nt][0] * sc, acc[nt][1] * sc);
            *(uint32_t*)&o[(row0 + 8) * HD_ + nt * 8 + 2 * qd] = packh2(acc[nt][2] * sc, acc[nt][3] * sc);
        }
    }
}

// ---------------------------------------------------------------------------
// Kernel 2: flash attention, all-fp16 mma (fp32 accum + softmax).
// grid (8, 96). block 256 = 8 warps. Q frags hoisted; next K/V tile
// prefetched to registers during softmax/PV; softmax in log2 domain.
// Qs[128][36] h2, Ks[64][36] h2, Vp[32][72] h2 (key-pairs).
// ---------------------------------------------------------------------------
__global__ __launch_bounds__(256, 2) void attn_mma_kernel()
{
    extern __shared__ __align__(16) uint32_t smu[];
    uint32_t* Qs = smu;              // 128*36
    uint32_t* Ks = Qs + 128 * 36;    // 64*36
    uint32_t* Vp = Ks + 64 * 36;     // 32*72

    const int bh = blockIdx.y;
    const int h  = bh % H_;
    const int b  = bh / H_;
    const int q0 = blockIdx.x * 128;
    const int t  = threadIdx.x;
    const int w  = t >> 5;
    const int lane = t & 31;
    const int g  = lane >> 2;
    const int qd = lane & 3;
    const int row0 = w * 16 + g;

    const uint32_t* Qg2 = (const uint32_t*)(g_q + ((size_t)bh * N_ + q0) * HD_);
    const uint32_t* Kg2 = (const uint32_t*)(g_k + (size_t)bh * N_ * HD_);
    const uint32_t* Vg2 = (const uint32_t*)(g_v + (size_t)bh * N_ * HD_);

    // Q tile: direct h2 copy into stride-36 layout
#pragma unroll
    for (int i = t; i < 128 * 8; i += 256) {
        int r = i >> 3, c = (i & 7) << 2;
        *(uint4*)&Qs[r * 36 + c] = *(const uint4*)&Qg2[r * 32 + c];
    }
    // K tile 0
#pragma unroll
    for (int i = t; i < 64 * 8; i += 256) {
        int r = i >> 3, c = (i & 7) << 2;
        *(uint4*)&Ks[r * 36 + c] = *(const uint4*)&Kg2[r * 32 + c];
    }
    // V tile 0: interleave key-pairs
    {
        int k2 = t >> 3, cg = t & 7;
        uint4 a = *(const uint4*)&Vg2[(2 * k2)     * 32 + cg * 4];
        uint4 bb = *(const uint4*)&Vg2[(2 * k2 + 1) * 32 + cg * 4];
        uint4 o0, o1;
        o0.x = __byte_perm(a.x, bb.x, 0x5410); o0.y = __byte_perm(a.x, bb.x, 0x7632);
        o0.z = __byte_perm(a.y, bb.y, 0x5410); o0.w = __byte_perm(a.y, bb.y, 0x7632);
        o1.x = __byte_perm(a.z, bb.z, 0x5410); o1.y = __byte_perm(a.z, bb.z, 0x7632);
        o1.z = __byte_perm(a.w, bb.w, 0x5410); o1.w = __byte_perm(a.w, bb.w, 0x7632);
        *(uint4*)&Vp[k2 * 72 + cg * 8]     = o0;
        *(uint4*)&Vp[k2 * 72 + cg * 8 + 4] = o1;
    }
    __syncthreads();

    // hoist Q fragments
    uint32_t qa[4][4];
#pragma unroll
    for (int kc = 0; kc < 4; kc++) {
        qa[kc][0] = Qs[(row0)     * 36 + kc * 8 + qd];
        qa[kc][1] = Qs[(row0 + 8) * 36 + kc * 8 + qd];
        qa[kc][2] = Qs[(row0)     * 36 + kc * 8 + qd + 4];
        qa[kc][3] = Qs[(row0 + 8) * 36 + kc * 8 + qd + 4];
    }

    float O[8][4];
#pragma unroll
    for (int dt = 0; dt < 8; dt++)
#pragma unroll
        for (int j = 0; j < 4; j++) O[dt][j] = 0.f;
    float m0 = -1e30f, m1 = -1e30f, l0 = 0.f, l1 = 0.f;

    for (int kt = 0; kt < N_ / 64; kt++) {
        // ---- S = Q K^T  (logits already in log2 domain via pre-scaled Q) ----
        float S[8][4];
#pragma unroll
        for (int nt = 0; nt < 8; nt++)
#pragma unroll
            for (int j = 0; j < 4; j++) S[nt][j] = 0.f;

#pragma unroll
        for (int kc = 0; kc < 4; kc++) {
#pragma unroll
            for (int nt = 0; nt < 8; nt++) {
                uint32_t b0 = Ks[(nt * 8 + g) * 36 + kc * 8 + qd];
                uint32_t b1 = Ks[(nt * 8 + g) * 36 + kc * 8 + qd + 4];
                mma_f16(S[nt], qa[kc][0], qa[kc][1], qa[kc][2], qa[kc][3], b0, b1);
            }
        }

        // ---- prefetch next K/V tile into registers ----
        uint4 kp0, kp1, vp0, vp1;
        const bool more = (kt + 1 < N_ / 64);
        if (more) {
            const uint32_t* Kn = Kg2 + (size_t)(kt + 1) * 64 * 32;
            const uint32_t* Vn = Vg2 + (size_t)(kt + 1) * 64 * 32;
            {
                int r = t >> 3, c = (t & 7) << 2;
                kp0 = *(const uint4*)&Kn[r * 32 + c];
                int u = t + 256;
                int r1 = u >> 3, c1 = (u & 7) << 2;
                kp1 = *(const uint4*)&Kn[r1 * 32 + c1];
            }
            {
                int k2 = t >> 3, cg = t & 7;
                vp0 = *(const uint4*)&Vn[(2 * k2)     * 32 + cg * 4];
                vp1 = *(const uint4*)&Vn[(2 * k2 + 1) * 32 + cg * 4];
            }
        }

        // ---- online softmax (log2 domain) ----
        float mx0 = -1e30f, mx1 = -1e30f;
#pragma unroll
        for (int nt = 0; nt < 8; nt++) {
            mx0 = fmaxf(mx0, fmaxf(S[nt][0], S[nt][1]));
            mx1 = fmaxf(mx1, fmaxf(S[nt][2], S[nt][3]));
        }
        mx0 = fmaxf(mx0, __shfl_xor_sync(0xffffffffu, mx0, 1));
        mx0 = fmaxf(mx0, __shfl_xor_sync(0xffffffffu, mx0, 2));
        mx1 = fmaxf(mx1, __shfl_xor_sync(0xffffffffu, mx1, 1));
        mx1 = fmaxf(mx1, __shfl_xor_sync(0xffffffffu, mx1, 2));

        float nm0 = fmaxf(m0, mx0), nm1 = fmaxf(m1, mx1);
        float corr0 = ex2f(m0 - nm0), corr1 = ex2f(m1 - nm1);
        m0 = nm0; m1 = nm1;

        float s0 = 0.f, s1 = 0.f;
#pragma unroll
        for (int nt = 0; nt < 8; nt++) {
            S[nt][0] = ex2f(S[nt][0] - nm0);
            S[nt][1] = ex2f(S[nt][1] - nm0);
            S[nt][2] = ex2f(S[nt][2] - nm1);
            S[nt][3] = ex2f(S[nt][3] - nm1);
            s0 += S[nt][0] + S[nt][1];
            s1 += S[nt][2] + S[nt][3];
        }
        s0 += __shfl_xor_sync(0xffffffffu, s0, 1);
        s0 += __shfl_xor_sync(0xffffffffu, s0, 2);
        s1 += __shfl_xor_sync(0xffffffffu, s1, 1);
        s1 += __shfl_xor_sync(0xffffffffu, s1, 2);
        l0 = l0 * corr0 + s0;
        l1 = l1 * corr1 + s1;

#pragma unroll
        for (int dt = 0; dt < 8; dt++) {
            O[dt][0] *= corr0; O[dt][1] *= corr0;
            O[dt][2] *= corr1; O[dt][3] *= corr1;
        }

        // ---- O += P V  (P packed from S fragments, register-resident) ----
#pragma unroll
        for (int c = 0; c < 4; c++) {
            uint32_t a0 = packh2(S[2 * c][0],     S[2 * c][1]);
            uint32_t a1 = packh2(S[2 * c][2],     S[2 * c][3]);
            uint32_t a2 = packh2(S[2 * c + 1][0], S[2 * c + 1][1]);
            uint32_t a3 = packh2(S[2 * c + 1][2], S[2 * c + 1][3]);
#pragma unroll
            for (int dt = 0; dt < 8; dt++) {
                uint32_t b0 = Vp[(8 * c + qd)     * 72 + dt * 8 + g];
                uint32_t b1 = Vp[(8 * c + 4 + qd) * 72 + dt * 8 + g];
                mma_f16(O[dt], a0, a1, a2, a3, b0, b1);
            }
        }

        // ---- commit prefetched tile to smem ----
        if (more) {
            __syncthreads();
            {
                int r = t >> 3, c = (t & 7) << 2;
                *(uint4*)&Ks[r * 36 + c] = kp0;
                int u = t + 256;
                int r1 = u >> 3, c1 = (u & 7) << 2;
                *(uint4*)&Ks[r1 * 36 + c1] = kp1;
            }
            {
                int k2 = t >> 3, cg = t & 7;
                uint4 o0, o1;
                o0.x = __byte_perm(vp0.x, vp1.x, 0x5410); o0.y = __byte_perm(vp0.x, vp1.x, 0x7632);
                o0.z = __byte_perm(vp0.y, vp1.y, 0x5410); o0.w = __byte_perm(vp0.y, vp1.y, 0x7632);
                o1.x = __byte_perm(vp0.z, vp1.z, 0x5410); o1.y = __byte_perm(vp0.z, vp1.z, 0x7632);
                o1.z = __byte_perm(vp0.w, vp1.w, 0x5410); o1.w = __byte_perm(vp0.w, vp1.w, 0x7632);
                *(uint4*)&Vp[k2 * 72 + cg * 8]     = o0;
                *(uint4*)&Vp[k2 * 72 + cg * 8 + 4] = o1;
            }
            __syncthreads();
        }
    }

    // normalize + store (half) in concat layout [B*N, D]
    float inv0 = 1.f / l0, inv1 = 1.f / l1;
    __half* Ao = g_att + ((size_t)b * N_ + q0) * D_ + h * HD_;
#pragma unroll
    for (int dt = 0; dt < 8; dt++) {
        *(uint32_t*)&Ao[(size_t)(row0)     * D_ + dt * 8 + 2 * qd] = packh2(O[dt][0] * inv0, O[dt][1] * inv0);
        *(uint32_t*)&Ao[(size_t)(row0 + 8) * D_ + dt * 8 + 2 * qd] = packh2(O[dt][2] * inv1, O[dt][3] * inv1);
    }
}

// ---------------------------------------------------------------------------
// Kernel 3: output projection, fp16 mma (fp32 accum + fp32 output).
// out[r, c] = sum_k A[r,k] * Wo[c,k] + bo[c];  A = g_att (half, concat).
// grid (12, 64). As[128][36] h2 (direct copy), Ws[64][36] h2 (k-pairs).
// ---------------------------------------------------------------------------
__global__ __launch_bounds__(256) void outproj_mma_kernel(
    const float* __restrict__ Wo, const float* __restrict__ bo,
    float* __restrict__ out)
{
    extern __shared__ __align__(16) uint32_t smu[];
    uint32_t* As = smu;              // 128*36
    uint32_t* Ws = As + 128 * 36;    // 64*36

    const int c0 = blockIdx.x * 64;
    const int r0 = blockIdx.y * 128;
    const int t  = threadIdx.x;
    const int w  = t >> 5;
    const int lane = t & 31;
    const int g  = lane >> 2;
    const int qd = lane & 3;
    const int row0 = w * 16 + g;

    const uint32_t* Ag2 = (const uint32_t*)g_att;   // row stride D_/2 = 384 h2

    float acc[8][4];
#pragma unroll
    for (int nt = 0; nt < 8; nt++) {
        float bb0 = bo[c0 + nt * 8 + 2 * qd];
        float bb1 = bo[c0 + nt * 8 + 2 * qd + 1];
        acc[nt][0] = bb0; acc[nt][1] = bb1; acc[nt][2] = bb0; acc[nt][3] = bb1;
    }

    for (int kt = 0; kt < D_ / 64; kt++) {
        __syncthreads();
        // A tile: direct h2 copy
#pragma unroll
        for (int i = t; i < 128 * 8; i += 256) {
            int r = i >> 3, c = (i & 7) << 2;
            *(uint4*)&As[r * 36 + c] = *(const uint4*)&Ag2[(size_t)(r0 + r) * 384 + kt * 32 + c];
        }
        // W tile: fp32 -> h2 (k-pairs contiguous in gmem)
#pragma unroll
        for (int i = t; i < 64 * 8; i += 256) {
            int r = i >> 3, c4 = (i & 7) << 2;   // r = out-col, c4 = h2 idx
            const float* src = &Wo[(size_t)(c0 + r) * D_ + kt * 64 + c4 * 2];
            float4 v0 = *(const float4*)src;
            float4 v1 = *(const float4*)(src + 4);
            uint4 pk;
            pk.x = packh2(v0.x, v0.y); pk.y = packh2(v0.z, v0.w);
            pk.z = packh2(v1.x, v1.y); pk.w = packh2(v1.z, v1.w);
            *(uint4*)&Ws[r * 36 + c4] = pk;
        }
        __syncthreads();

#pragma unroll
        for (int kc = 0; kc < 4; kc++) {
            uint32_t a0 = As[(row0)     * 36 + kc * 8 + qd];
            uint32_t a1 = As[(row0 + 8) * 36 + kc * 8 + qd];
            uint32_t a2 = As[(row0)     * 36 + kc * 8 + qd + 4];
            uint32_t a3 = As[(row0 + 8) * 36 + kc * 8 + qd + 4];
#pragma unroll
            for (int nt = 0; nt < 8; nt++) {
                uint32_t b0 = Ws[(nt * 8 + g) * 36 + kc * 8 + qd];
                uint32_t b1 = Ws[(nt * 8 + g) * 36 + kc * 8 + qd + 4];
                mma_f16(acc[nt], a0, a1, a2, a3, b0, b1);
            }
        }
    }

#pragma unroll
    for (int nt = 0; nt < 8; nt++) {
        float2 u0 = make_float2(acc[nt][0], acc[nt][1]);
        float2 u1 = make_float2(acc[nt][2], acc[nt][3]);
        *(float2*)&out[(size_t)(r0 + row0)     * D_ + c0 + nt * 8 + 2 * qd] = u0;
        *(float2*)&out[(size_t)(r0 + row0 + 8) * D_ + c0 + nt * 8 + 2 * qd] = u1;
    }
}

// ---------------------------------------------------------------------------
extern "C" void kernel_launch(void* const* d_in, const int* in_sizes, int n_in,
                              void* d_out, int out_size)
{
    const float* x  = (const float*)d_in[0];
    const float* Wq = (const float*)d_in[1];
    const float* Wk = (const float*)d_in[2];
    const float* Wv = (const float*)d_in[3];
    const float* bq = (const float*)d_in[4];
    const float* bk = (const float*)d_in[5];
    const float* bv = (const float*)d_in[6];
    const float* Wo = (const float*)d_in[7];
    const float* bo = (const float*)d_in[8];
    float* out = (float*)d_out;

    const int proj_smem = (128 * 36 + 64 * 36) * 4;               // 27648
    const int attn_smem = (128 * 36 + 64 * 36 + 32 * 72) * 4;     // 36864
    cudaFuncSetAttribute(qkv_mma_kernel, cudaFuncAttributeMaxDynamicSharedMemorySize, proj_smem);
    cudaFuncSetAttribute(attn_mma_kernel, cudaFuncAttributeMaxDynamicSharedMemorySize, attn_smem);
    cudaFuncSetAttribute(outproj_mma_kernel, cudaFuncAttributeMaxDynamicSharedMemorySize, proj_smem);

    qkv_mma_kernel<<<dim3(N_ / 128, B_ * H_), 256, proj_smem>>>(x, Wq, Wk, Wv, bq, bk, bv);
    attn_mma_kernel<<<dim3(N_ / 128, B_ * H_), 256, attn_smem>>>();
    outproj_mma_kernel<<<dim3(D_ / 64, (B_ * N_) / 128), 256, proj_smem>>>(Wo, bo, out);
}

// round 6
// speedup vs baseline: 6.4353x; 1.1415x over previous
#include <cuda_runtime.h>
#include <cuda_fp16.h>
#include <cstdint>

#define B_ 8
#define N_ 1024
#define D_ 768
#define H_ 12
#define HD_ 64

// Scratch (allocation-free rule: __device__ globals) — fp16 intermediates
__device__ __half g_q[B_ * H_ * N_ * HD_];       // pre-scaled by D^-0.5 * log2e
__device__ __half g_k[B_ * H_ * N_ * HD_];
__device__ __half g_v[B_ * H_ * N_ * HD_];
__device__ __half g_att[B_ * N_ * D_];           // concat layout [B*N, D]
__device__ uint32_t g_wqkv[3 * H_ * 64 * 32];    // [m][h][e][d2] half2, transposed
__device__ uint32_t g_wo[D_ * (D_ / 2)];         // [c][k2] half2

// ---------------------------------------------------------------------------
// helpers
// ---------------------------------------------------------------------------
__device__ __forceinline__ float ex2f(float x) {
    float y;
    asm("ex2.approx.ftz.f32 %0, %1;" : "=f"(y) : "f"(x));
    return y;
}

__device__ __forceinline__ void mma_f16(float c[4],
                                        uint32_t a0, uint32_t a1, uint32_t a2, uint32_t a3,
                                        uint32_t b0, uint32_t b1) {
    asm volatile(
        "mma.sync.aligned.m16n8k16.row.col.f32.f16.f16.f32 "
        "{%0,%1,%2,%3},{%4,%5,%6,%7},{%8,%9},{%0,%1,%2,%3};\n"
        : "+f"(c[0]), "+f"(c[1]), "+f"(c[2]), "+f"(c[3])
        : "r"(a0), "r"(a1), "r"(a2), "r"(a3), "r"(b0), "r"(b1));
}

__device__ __forceinline__ uint32_t packh2(float lo, float hi) {
    __half2 h = __floats2half2_rn(lo, hi);
    return *(uint32_t*)&h;
}

__device__ __forceinline__ void ldsm_x4(uint32_t& r0, uint32_t& r1, uint32_t& r2, uint32_t& r3,
                                        uint32_t addr) {
    asm volatile("ldmatrix.sync.aligned.m8n8.x4.shared.b16 {%0,%1,%2,%3}, [%4];"
                 : "=r"(r0), "=r"(r1), "=r"(r2), "=r"(r3) : "r"(addr));
}

__device__ __forceinline__ void ldsm_x4_t(uint32_t& r0, uint32_t& r1, uint32_t& r2, uint32_t& r3,
                                          uint32_t addr) {
    asm volatile("ldmatrix.sync.aligned.m8n8.x4.trans.shared.b16 {%0,%1,%2,%3}, [%4];"
                 : "=r"(r0), "=r"(r1), "=r"(r2), "=r"(r3) : "r"(addr));
}

// ---------------------------------------------------------------------------
// Prep kernels: pack weights to fp16 once per launch.
// ---------------------------------------------------------------------------
__global__ __launch_bounds__(256) void pack_wqkv_kernel(
    const float* __restrict__ Wq, const float* __restrict__ Wk, const float* __restrict__ Wv)
{
    int idx = blockIdx.x * 256 + threadIdx.x;          // [m][h][e][d2]
    if (idx >= 3 * H_ * 64 * 32) return;
    int d2 = idx & 31;
    int e  = (idx >> 5) & 63;
    int h  = (idx >> 11) % H_;
    int m  = idx / (H_ * 64 * 32);
    const float* W = (m == 0 ? Wq : (m == 1 ? Wk : Wv)) + h * HD_ * HD_;
    g_wqkv[idx] = packh2(W[(2 * d2) * 64 + e], W[(2 * d2 + 1) * 64 + e]);
}

__global__ __launch_bounds__(256) void pack_wo_kernel(const float* __restrict__ Wo)
{
    int idx = blockIdx.x * 256 + threadIdx.x;          // [c][k2]
    if (idx >= D_ * (D_ / 2)) return;
    float2 v = *(const float2*)&Wo[2 * idx];
    g_wo[idx] = packh2(v.x, v.y);
}

// ---------------------------------------------------------------------------
// Kernel 1: per-head QKV projection. One sync; W tiles are direct u4 copies
// of pre-packed fp16; all fragments via ldmatrix.
// grid (8, 96). block 256 = 8 warps.
// ---------------------------------------------------------------------------
__global__ __launch_bounds__(256) void qkv_mma_kernel(
    const float* __restrict__ x,
    const float* __restrict__ bq, const float* __restrict__ bk, const float* __restrict__ bv)
{
    extern __shared__ __align__(16) uint32_t smu[];
    uint32_t* Xs = smu;              // [128][36]
    uint32_t* Wsm = Xs + 128 * 36;   // 3 x [64][36]

    const int bh = blockIdx.y;
    const int h  = bh % H_;
    const int b  = bh / H_;
    const int n0 = blockIdx.x * 128;
    const int t  = threadIdx.x;
    const int w  = t >> 5;
    const int lane = t & 31;
    const int g  = lane >> 2;
    const int qd = lane & 3;
    const int row0 = w * 16 + g;

    const uint32_t Xs_a = (uint32_t)__cvta_generic_to_shared(Xs);
    const uint32_t Ws_a = (uint32_t)__cvta_generic_to_shared(Wsm);

    // X tile: fp32 -> half2
#pragma unroll
    for (int i = t; i < 128 * 8; i += 256) {
        int r = i >> 3, c8 = (i & 7) << 3;
        const float* src = &x[(b * N_ + n0 + r) * D_ + h * HD_ + c8];
        float4 v0 = *(const float4*)src;
        float4 v1 = *(const float4*)(src + 4);
        uint4 pk;
        pk.x = packh2(v0.x, v0.y); pk.y = packh2(v0.z, v0.w);
        pk.z = packh2(v1.x, v1.y); pk.w = packh2(v1.z, v1.w);
        *(uint4*)&Xs[r * 36 + ((i & 7) << 2)] = pk;
    }
    // 3 W tiles: direct copies (stride remap 32 -> 36)
#pragma unroll
    for (int i = t; i < 3 * 512; i += 256) {
        int m = i >> 9, j = i & 511;
        int r = j >> 3, c = (j & 7) << 2;
        *(uint4*)&Wsm[m * 64 * 36 + r * 36 + c] =
            *(const uint4*)&g_wqkv[(m * H_ + h) * 64 * 32 + r * 32 + c];
    }
    __syncthreads();

    // hoist X fragments via ldmatrix
    uint32_t xa[4][4];
    {
        const uint32_t aoff = ((w * 16 + (lane & 15)) * 36 + (lane >> 4) * 4) * 4;
#pragma unroll
        for (int kc = 0; kc < 4; kc++)
            ldsm_x4(xa[kc][0], xa[kc][1], xa[kc][2], xa[kc][3], Xs_a + aoff + kc * 32);
    }

    const float* bm[3] = {bq, bk, bv};
    __half*      om[3] = {g_q, g_k, g_v};
    const float qscale = rsqrtf((float)D_) * 1.4426950408889634f;  // full-dim quirk * log2e

    const int mB = lane >> 3, rB = lane & 7;   // B-frag lane decomposition

#pragma unroll
    for (int m = 0; m < 3; m++) {
        const float* bias = bm[m] + h * HD_;
        float acc[8][4];
#pragma unroll
        for (int nt = 0; nt < 8; nt++) {
            float bb0 = bias[nt * 8 + 2 * qd];
            float bb1 = bias[nt * 8 + 2 * qd + 1];
            acc[nt][0] = bb0; acc[nt][1] = bb1; acc[nt][2] = bb0; acc[nt][3] = bb1;
        }

        const uint32_t wbase = Ws_a + m * 64 * 36 * 4;
#pragma unroll
        for (int kc = 0; kc < 4; kc++) {
#pragma unroll
            for (int c = 0; c < 4; c++) {
                uint32_t b0, b1, b2, b3;
                uint32_t addr = wbase +
                    (((2 * c + (mB >> 1)) * 8 + rB) * 36 + kc * 8 + (mB & 1) * 4) * 4;
                ldsm_x4(b0, b1, b2, b3, addr);
                mma_f16(acc[2 * c],     xa[kc][0], xa[kc][1], xa[kc][2], xa[kc][3], b0, b1);
                mma_f16(acc[2 * c + 1], xa[kc][0], xa[kc][1], xa[kc][2], xa[kc][3], b2, b3);
            }
        }

        const float sc = (m == 0) ? qscale : 1.0f;
        __half* o = om[m] + ((size_t)bh * N_ + n0) * HD_;
#pragma unroll
        for (int nt = 0; nt < 8; nt++) {
            *(uint32_t*)&o[(row0)     * HD_ + nt * 8 + 2 * qd] = packh2(acc[nt][0] * sc, acc[nt][1] * sc);
            *(uint32_t*)&o[(row0 + 8) * HD_ + nt * 8 + 2 * qd] = packh2(acc[nt][2] * sc, acc[nt][3] * sc);
        }
    }
}

// ---------------------------------------------------------------------------
// Kernel 2: flash attention, fp16 mma, ldmatrix fragment feeds.
// V in natural layout (ldmatrix.trans for B-frags). Register prefetch of
// next K/V tile. Softmax in log2 domain (scale pre-folded into Q).
// grid (8, 96). block 256 = 8 warps.
// ---------------------------------------------------------------------------
__global__ __launch_bounds__(256, 2) void attn_mma_kernel()
{
    extern __shared__ __align__(16) uint32_t smu[];
    uint32_t* Qs = smu;              // [128][36]
    uint32_t* Ks = Qs + 128 * 36;    // [64][36]
    uint32_t* Vs = Ks + 64 * 36;     // [64][36] natural layout

    const int bh = blockIdx.y;
    const int h  = bh % H_;
    const int b  = bh / H_;
    const int q0 = blockIdx.x * 128;
    const int t  = threadIdx.x;
    const int w  = t >> 5;
    const int lane = t & 31;
    const int g  = lane >> 2;
    const int qd = lane & 3;
    const int row0 = w * 16 + g;

    const uint32_t Qs_a = (uint32_t)__cvta_generic_to_shared(Qs);
    const uint32_t Ks_a = (uint32_t)__cvta_generic_to_shared(Ks);
    const uint32_t Vs_a = (uint32_t)__cvta_generic_to_shared(Vs);

    const uint32_t* Qg2 = (const uint32_t*)(g_q + ((size_t)bh * N_ + q0) * HD_);
    const uint32_t* Kg2 = (const uint32_t*)(g_k + (size_t)bh * N_ * HD_);
    const uint32_t* Vg2 = (const uint32_t*)(g_v + (size_t)bh * N_ * HD_);

    // copy indices (uint4 granularity)
    const int rA = t >> 3,        cA = (t & 7) << 2;       // +256: second half
    // Q tile
#pragma unroll
    for (int i = t; i < 128 * 8; i += 256) {
        int r = i >> 3, c = (i & 7) << 2;
        *(uint4*)&Qs[r * 36 + c] = *(const uint4*)&Qg2[r * 32 + c];
    }
    // K/V tile 0
    {
        *(uint4*)&Ks[rA * 36 + cA] = *(const uint4*)&Kg2[rA * 32 + cA];
        *(uint4*)&Vs[rA * 36 + cA] = *(const uint4*)&Vg2[rA * 32 + cA];
        int u = t + 256;
        int r1 = u >> 3, c1 = (u & 7) << 2;
        *(uint4*)&Ks[r1 * 36 + c1] = *(const uint4*)&Kg2[r1 * 32 + c1];
        *(uint4*)&Vs[r1 * 36 + c1] = *(const uint4*)&Vg2[r1 * 32 + c1];
    }
    __syncthreads();

    // hoist Q fragments
    uint32_t qa[4][4];
    {
        const uint32_t aoff = ((w * 16 + (lane & 15)) * 36 + (lane >> 4) * 4) * 4;
#pragma unroll
        for (int kc = 0; kc < 4; kc++)
            ldsm_x4(qa[kc][0], qa[kc][1], qa[kc][2], qa[kc][3], Qs_a + aoff + kc * 32);
    }

    const int mB = lane >> 3, rB = lane & 7;

    float O[8][4];
#pragma unroll
    for (int dt = 0; dt < 8; dt++)
#pragma unroll
        for (int j = 0; j < 4; j++) O[dt][j] = 0.f;
    float m0 = -1e30f, m1 = -1e30f, l0 = 0.f, l1 = 0.f;

    for (int kt = 0; kt < N_ / 64; kt++) {
        // ---- S = Q K^T ----
        float S[8][4];
#pragma unroll
        for (int nt = 0; nt < 8; nt++)
#pragma unroll
            for (int j = 0; j < 4; j++) S[nt][j] = 0.f;

#pragma unroll
        for (int kc = 0; kc < 4; kc++) {
#pragma unroll
            for (int c = 0; c < 4; c++) {
                uint32_t b0, b1, b2, b3;
                uint32_t addr = Ks_a +
                    (((2 * c + (mB >> 1)) * 8 + rB) * 36 + kc * 8 + (mB & 1) * 4) * 4;
                ldsm_x4(b0, b1, b2, b3, addr);
                mma_f16(S[2 * c],     qa[kc][0], qa[kc][1], qa[kc][2], qa[kc][3], b0, b1);
                mma_f16(S[2 * c + 1], qa[kc][0], qa[kc][1], qa[kc][2], qa[kc][3], b2, b3);
            }
        }

        // ---- prefetch next K/V tile into registers ----
        uint4 kp0, kp1, vp0, vp1;
        const bool more = (kt + 1 < N_ / 64);
        if (more) {
            const uint32_t* Kn = Kg2 + (size_t)(kt + 1) * 64 * 32;
            const uint32_t* Vn = Vg2 + (size_t)(kt + 1) * 64 * 32;
            kp0 = *(const uint4*)&Kn[rA * 32 + cA];
            vp0 = *(const uint4*)&Vn[rA * 32 + cA];
            int u = t + 256;
            int r1 = u >> 3, c1 = (u & 7) << 2;
            kp1 = *(const uint4*)&Kn[r1 * 32 + c1];
            vp1 = *(const uint4*)&Vn[r1 * 32 + c1];
        }

        // ---- online softmax (log2 domain) ----
        float mx0 = -1e30f, mx1 = -1e30f;
#pragma unroll
        for (int nt = 0; nt < 8; nt++) {
            mx0 = fmaxf(mx0, fmaxf(S[nt][0], S[nt][1]));
            mx1 = fmaxf(mx1, fmaxf(S[nt][2], S[nt][3]));
        }
        mx0 = fmaxf(mx0, __shfl_xor_sync(0xffffffffu, mx0, 1));
        mx0 = fmaxf(mx0, __shfl_xor_sync(0xffffffffu, mx0, 2));
        mx1 = fmaxf(mx1, __shfl_xor_sync(0xffffffffu, mx1, 1));
        mx1 = fmaxf(mx1, __shfl_xor_sync(0xffffffffu, mx1, 2));

        float nm0 = fmaxf(m0, mx0), nm1 = fmaxf(m1, mx1);
        float corr0 = ex2f(m0 - nm0), corr1 = ex2f(m1 - nm1);
        m0 = nm0; m1 = nm1;

        float s0 = 0.f, s1 = 0.f;
#pragma unroll
        for (int nt = 0; nt < 8; nt++) {
            S[nt][0] = ex2f(S[nt][0] - nm0);
            S[nt][1] = ex2f(S[nt][1] - nm0);
            S[nt][2] = ex2f(S[nt][2] - nm1);
            S[nt][3] = ex2f(S[nt][3] - nm1);
            s0 += S[nt][0] + S[nt][1];
            s1 += S[nt][2] + S[nt][3];
        }
        s0 += __shfl_xor_sync(0xffffffffu, s0, 1);
        s0 += __shfl_xor_sync(0xffffffffu, s0, 2);
        s1 += __shfl_xor_sync(0xffffffffu, s1, 1);
        s1 += __shfl_xor_sync(0xffffffffu, s1, 2);
        l0 = l0 * corr0 + s0;
        l1 = l1 * corr1 + s1;

#pragma unroll
        for (int dt = 0; dt < 8; dt++) {
            O[dt][0] *= corr0; O[dt][1] *= corr0;
            O[dt][2] *= corr1; O[dt][3] *= corr1;
        }

        // ---- O += P V (P register-packed; V b-frags via ldmatrix.trans) ----
#pragma unroll
        for (int c = 0; c < 4; c++) {
            uint32_t a0 = packh2(S[2 * c][0],     S[2 * c][1]);
            uint32_t a1 = packh2(S[2 * c][2],     S[2 * c][3]);
            uint32_t a2 = packh2(S[2 * c + 1][0], S[2 * c + 1][1]);
            uint32_t a3 = packh2(S[2 * c + 1][2], S[2 * c + 1][3]);
#pragma unroll
            for (int e = 0; e < 4; e++) {
                uint32_t b0, b1, b2, b3;
                uint32_t addr = Vs_a +
                    (((16 * c + (mB & 1) * 8 + rB)) * 36 + (2 * e + (mB >> 1)) * 4) * 4;
                ldsm_x4_t(b0, b1, b2, b3, addr);
                mma_f16(O[2 * e],     a0, a1, a2, a3, b0, b1);
                mma_f16(O[2 * e + 1], a0, a1, a2, a3, b2, b3);
            }
        }

        // ---- commit prefetched tile ----
        if (more) {
            __syncthreads();
            *(uint4*)&Ks[rA * 36 + cA] = kp0;
            *(uint4*)&Vs[rA * 36 + cA] = vp0;
            int u = t + 256;
            int r1 = u >> 3, c1 = (u & 7) << 2;
            *(uint4*)&Ks[r1 * 36 + c1] = kp1;
            *(uint4*)&Vs[r1 * 36 + c1] = vp1;
            __syncthreads();
        }
    }

    // normalize + store (half) in concat layout [B*N, D]
    float inv0 = 1.f / l0, inv1 = 1.f / l1;
    __half* Ao = g_att + ((size_t)b * N_ + q0) * D_ + h * HD_;
#pragma unroll
    for (int dt = 0; dt < 8; dt++) {
        *(uint32_t*)&Ao[(size_t)(row0)     * D_ + dt * 8 + 2 * qd] = packh2(O[dt][0] * inv0, O[dt][1] * inv0);
        *(uint32_t*)&Ao[(size_t)(row0 + 8) * D_ + dt * 8 + 2 * qd] = packh2(O[dt][2] * inv1, O[dt][3] * inv1);
    }
}

// ---------------------------------------------------------------------------
// Kernel 3: output projection, fp16 mma, ldmatrix feeds, pre-packed Wo.
// grid (12, 64). block 256 = 8 warps.
// ---------------------------------------------------------------------------
__global__ __launch_bounds__(256) void outproj_mma_kernel(
    const float* __restrict__ bo, float* __restrict__ out)
{
    extern __shared__ __align__(16) uint32_t smu[];
    uint32_t* As = smu;              // [128][36]
    uint32_t* Ws = As + 128 * 36;    // [64][36]

    const int c0 = blockIdx.x * 64;
    const int r0 = blockIdx.y * 128;
    const int t  = threadIdx.x;
    const int w  = t >> 5;
    const int lane = t & 31;
    const int g  = lane >> 2;
    const int qd = lane & 3;
    const int row0 = w * 16 + g;

    const uint32_t As_a = (uint32_t)__cvta_generic_to_shared(As);
    const uint32_t Ws_a = (uint32_t)__cvta_generic_to_shared(Ws);
    const uint32_t* Ag2 = (const uint32_t*)g_att;   // row stride 384 u32

    const int mB = lane >> 3, rB = lane & 7;

    float acc[8][4];
#pragma unroll
    for (int nt = 0; nt < 8; nt++) {
        float bb0 = bo[c0 + nt * 8 + 2 * qd];
        float bb1 = bo[c0 + nt * 8 + 2 * qd + 1];
        acc[nt][0] = bb0; acc[nt][1] = bb1; acc[nt][2] = bb0; acc[nt][3] = bb1;
    }

    for (int kt = 0; kt < D_ / 64; kt++) {
        __syncthreads();
#pragma unroll
        for (int i = t; i < 128 * 8; i += 256) {
            int r = i >> 3, c = (i & 7) << 2;
            *(uint4*)&As[r * 36 + c] = *(const uint4*)&Ag2[(size_t)(r0 + r) * 384 + kt * 32 + c];
        }
#pragma unroll
        for (int i = t; i < 64 * 8; i += 256) {
            int r = i >> 3, c = (i & 7) << 2;
            *(uint4*)&Ws[r * 36 + c] = *(const uint4*)&g_wo[(size_t)(c0 + r) * 384 + kt * 32 + c];
        }
        __syncthreads();

        const uint32_t aoff = ((w * 16 + (lane & 15)) * 36 + (lane >> 4) * 4) * 4;
#pragma unroll
        for (int kc = 0; kc < 4; kc++) {
            uint32_t a0, a1, a2, a3;
            ldsm_x4(a0, a1, a2, a3, As_a + aoff + kc * 32);
#pragma unroll
            for (int c = 0; c < 4; c++) {
                uint32_t b0, b1, b2, b3;
                uint32_t addr = Ws_a +
                    (((2 * c + (mB >> 1)) * 8 + rB) * 36 + kc * 8 + (mB & 1) * 4) * 4;
                ldsm_x4(b0, b1, b2, b3, addr);
                mma_f16(acc[2 * c],     a0, a1, a2, a3, b0, b1);
                mma_f16(acc[2 * c + 1], a0, a1, a2, a3, b2, b3);
            }
        }
    }

#pragma unroll
    for (int nt = 0; nt < 8; nt++) {
        float2 u0 = make_float2(acc[nt][0], acc[nt][1]);
        float2 u1 = make_float2(acc[nt][2], acc[nt][3]);
        *(float2*)&out[(size_t)(r0 + row0)     * D_ + c0 + nt * 8 + 2 * qd] = u0;
        *(float2*)&out[(size_t)(r0 + row0 + 8) * D_ + c0 + nt * 8 + 2 * qd] = u1;
    }
}

// ---------------------------------------------------------------------------
extern "C" void kernel_launch(void* const* d_in, const int* in_sizes, int n_in,
                              void* d_out, int out_size)
{
    const float* x  = (const float*)d_in[0];
    const float* Wq = (const float*)d_in[1];
    const float* Wk = (const float*)d_in[2];
    const float* Wv = (const float*)d_in[3];
    const float* bq = (const float*)d_in[4];
    const float* bk = (const float*)d_in[5];
    const float* bv = (const float*)d_in[6];
    const float* Wo = (const float*)d_in[7];
    const float* bo = (const float*)d_in[8];
    float* out = (float*)d_out;

    const int qkv_smem  = (128 * 36 + 3 * 64 * 36) * 4;   // 46080
    const int attn_smem = (128 * 36 + 2 * 64 * 36) * 4;   // 36864
    const int outp_smem = (128 * 36 + 64 * 36) * 4;       // 27648
    cudaFuncSetAttribute(qkv_mma_kernel, cudaFuncAttributeMaxDynamicSharedMemorySize, qkv_smem);
    cudaFuncSetAttribute(attn_mma_kernel, cudaFuncAttributeMaxDynamicSharedMemorySize, attn_smem);
    cudaFuncSetAttribute(outproj_mma_kernel, cudaFuncAttributeMaxDynamicSharedMemorySize, outp_smem);

    pack_wqkv_kernel<<<(3 * H_ * 64 * 32 + 255) / 256, 256>>>(Wq, Wk, Wv);
    pack_wo_kernel<<<(D_ * (D_ / 2) + 255) / 256, 256>>>(Wo);
    qkv_mma_kernel<<<dim3(N_ / 128, B_ * H_), 256, qkv_smem>>>(x, bq, bk, bv);
    attn_mma_kernel<<<dim3(N_ / 128, B_ * H_), 256, attn_smem>>>();
    outproj_mma_kernel<<<dim3(D_ / 64, (B_ * N_) / 128), 256, outp_smem>>>(bo, out);
}